// round 10
// baseline (speedup 1.0000x reference)
#include <cuda_runtime.h>
#include <cstdint>

#define NNODES 100000
#define NEDGES 640000
#define FIN 128
#define FOUT 64
#define BN_EPS 1e-5f

// ---------------- scratch (static device globals; no runtime allocation) ----
__device__ float g_h[(size_t)NNODES * FIN];     // x @ W_gcn
__device__ float g_agg[(size_t)NNODES * FIN];   // aggregated messages
__device__ float g_t[(size_t)NNODES * FOUT];    // hidden after GEMM2
__device__ int   g_degi[NNODES];
__device__ float g_dinv[NNODES];
__device__ int   g_off[NNODES + 1];
__device__ int   g_cursor[NNODES];
__device__ int   g_alloc;
__device__ int   g_elist[NEDGES];
__device__ float g_sum1[FIN], g_sq1[FIN], g_a1[FIN], g_c1[FIN];
__device__ float g_sum2[FOUT], g_sq2[FOUT], g_a2[FOUT], g_c2[FOUT];

// ---------------- zero ------------------------------------------------------
__global__ void zero_kernel(int M) {
    int i = blockIdx.x * blockDim.x + threadIdx.x;
    for (int j = i; j < M; j += gridDim.x * blockDim.x) g_degi[j] = 0;
    if (i < FIN)  { g_sum1[i] = 0.f; g_sq1[i] = 0.f; }
    if (i < FOUT) { g_sum2[i] = 0.f; g_sq2[i] = 0.f; }
    if (i == 0) g_alloc = 0;
}

// ---------------- in-degree count -------------------------------------------
__global__ void deg_kernel(const int* __restrict__ dst, int E, int M) {
    int e = blockIdx.x * blockDim.x + threadIdx.x;
    if (e < E) {
        int d = dst[e];
        if ((unsigned)d < (unsigned)M) atomicAdd(&g_degi[d], 1);
    }
}

// ---------------- CSR segment allocation (warp-aggregated) ------------------
// Replaces the 3-kernel prefix scan: segment order is irrelevant, only
// per-node contiguity matters. One atomicAdd per warp.
__global__ void alloc_kernel(int M) {
    int i = blockIdx.x * blockDim.x + threadIdx.x;
    int lane = threadIdx.x & 31;
    int deg = 0;
    if (i < M) deg = g_degi[i];
    int incl = deg;
    #pragma unroll
    for (int o = 1; o < 32; o <<= 1) {
        int v = __shfl_up_sync(0xffffffffu, incl, o);
        if (lane >= o) incl += v;
    }
    int total = __shfl_sync(0xffffffffu, incl, 31);
    int base = 0;
    if (lane == 0) base = atomicAdd(&g_alloc, total);
    base = __shfl_sync(0xffffffffu, base, 0);
    if (i < M) {
        int o = base + incl - deg;
        g_off[i] = o;
        g_cursor[i] = o;
        g_dinv[i] = rsqrtf((float)deg + 1.0f);  // +1 = self loop
    }
}

// ---------------- edge-list fill --------------------------------------------
__global__ void fill_kernel(const int* __restrict__ src, const int* __restrict__ dst,
                            int E, int M) {
    int e = blockIdx.x * blockDim.x + threadIdx.x;
    if (e < E) {
        int s = src[e];
        int d = dst[e];
        if ((unsigned)s < (unsigned)M && (unsigned)d < (unsigned)M) {
            int p = atomicAdd(&g_cursor[d], 1);
            g_elist[p] = s;
        }
    }
}

// ---------------- gather (R4 exact) -----------------------------------------
__global__ void gather_kernel(int M) {
    int warp = (blockIdx.x * blockDim.x + threadIdx.x) >> 5;
    int lane = threadIdx.x & 31;
    if (warp >= M) return;
    int d = warp;
    int e0 = g_off[d];
    int e1 = g_cursor[d];
    float4 acc = make_float4(0.f, 0.f, 0.f, 0.f);
    for (int e = e0; e < e1; e++) {
        int s = g_elist[e];
        float ws = g_dinv[s];
        float4 v = *(const float4*)&g_h[(size_t)s * FIN + lane * 4];
        acc.x = fmaf(v.x, ws, acc.x);
        acc.y = fmaf(v.y, ws, acc.y);
        acc.z = fmaf(v.z, ws, acc.z);
        acc.w = fmaf(v.w, ws, acc.w);
    }
    float wd = g_dinv[d];
    float4 vs = *(const float4*)&g_h[(size_t)d * FIN + lane * 4];
    float4 o;
    o.x = wd * acc.x + wd * wd * vs.x;
    o.y = wd * acc.y + wd * wd * vs.y;
    o.z = wd * acc.z + wd * wd * vs.z;
    o.w = wd * acc.w + wd * wd * vs.w;
    *(float4*)&g_agg[(size_t)d * FIN + lane * 4] = o;
}

// ---------------- per-column sum / sumsq (BN1 only) -------------------------
template <int F>
__global__ void stats_kernel(const float* __restrict__ X, int M,
                             float* __restrict__ sum, float* __restrict__ sq) {
    constexpr int RP = 256 / F;
    int col  = threadIdx.x % F;
    int rsub = threadIdx.x / F;
    float s = 0.f, q = 0.f;
    for (int r = blockIdx.x * RP + rsub; r < M; r += gridDim.x * RP) {
        float v = X[(size_t)r * F + col];
        s += v; q += v * v;
    }
    __shared__ float sh[256];
    sh[threadIdx.x] = s; __syncthreads();
    if (rsub == 0) {
        #pragma unroll
        for (int k = 1; k < RP; k++) s += sh[k * F + col];
    }
    __syncthreads();
    sh[threadIdx.x] = q; __syncthreads();
    if (rsub == 0) {
        #pragma unroll
        for (int k = 1; k < RP; k++) q += sh[k * F + col];
        atomicAdd(&sum[col], s);
        atomicAdd(&sq[col],  q);
    }
}

template <int F>
__global__ void finalize_kernel(const float* __restrict__ sum, const float* __restrict__ sq,
                                const float* __restrict__ gamma, const float* __restrict__ beta,
                                int M, float* __restrict__ a, float* __restrict__ c) {
    int i = threadIdx.x;
    if (i < F) {
        float mean = sum[i] / (float)M;
        float var  = sq[i] / (float)M - mean * mean;
        float s = gamma[i] * rsqrtf(var + BN_EPS);
        a[i] = s;
        c[i] = beta[i] - mean * s;
    }
}

// ---------------- tf32 helpers ----------------------------------------------
__device__ __forceinline__ uint32_t f_tf32(float x) {
    uint32_t y;
    asm("cvt.rna.tf32.f32 %0, %1;" : "=r"(y) : "f"(x));
    return y;
}

// ---------------- tf32 tensor GEMM1: h = x @ W  (M x 128 x 128) -------------
__global__ __launch_bounds__(256) void tgemm1_kernel(
    const float* __restrict__ A, const float* __restrict__ B, float* __restrict__ C, int M) {
    constexpr int BM = 128, BN = 128, BK = 32;
    __shared__ uint32_t As[BM][BK + 4];
    __shared__ uint32_t Bs[BK][BN + 8];

    int tid = threadIdx.x;
    int lane = tid & 31, wid = tid >> 5;
    int wr = wid & 3, wc = wid >> 2;        // warp tile: 32 rows x 64 cols
    int m0 = wr * 32, n0 = wc * 64;
    int row0 = blockIdx.x * BM;
    int grp = lane >> 2, tig = lane & 3;

    float acc[2][8][4];
    #pragma unroll
    for (int i = 0; i < 2; i++)
        #pragma unroll
        for (int j = 0; j < 8; j++)
            #pragma unroll
            for (int r = 0; r < 4; r++) acc[i][j][r] = 0.f;

    for (int k0 = 0; k0 < 128; k0 += BK) {
        #pragma unroll
        for (int p = 0; p < 4; p++) {
            int f = tid + p * 256;
            int r = f >> 3;
            int c4 = (f & 7) * 4;
            float4 v = make_float4(0.f, 0.f, 0.f, 0.f);
            if (row0 + r < M) v = *(const float4*)&A[(size_t)(row0 + r) * 128 + k0 + c4];
            As[r][c4 + 0] = f_tf32(v.x); As[r][c4 + 1] = f_tf32(v.y);
            As[r][c4 + 2] = f_tf32(v.z); As[r][c4 + 3] = f_tf32(v.w);
        }
        #pragma unroll
        for (int p = 0; p < 4; p++) {
            int f = tid + p * 256;
            int kr = f >> 5;
            int c4 = (f & 31) * 4;
            float4 v = *(const float4*)&B[(size_t)(k0 + kr) * 128 + c4];
            Bs[kr][c4 + 0] = f_tf32(v.x); Bs[kr][c4 + 1] = f_tf32(v.y);
            Bs[kr][c4 + 2] = f_tf32(v.z); Bs[kr][c4 + 3] = f_tf32(v.w);
        }
        __syncthreads();

        #pragma unroll
        for (int ks = 0; ks < BK / 8; ks++) {
            int kb = ks * 8;
            uint32_t a[2][4];
            #pragma unroll
            for (int mi = 0; mi < 2; mi++) {
                int r = m0 + mi * 16 + grp;
                a[mi][0] = As[r    ][kb + tig    ];
                a[mi][1] = As[r + 8][kb + tig    ];
                a[mi][2] = As[r    ][kb + tig + 4];
                a[mi][3] = As[r + 8][kb + tig + 4];
            }
            uint32_t b[8][2];
            #pragma unroll
            for (int ni = 0; ni < 8; ni++) {
                int n = n0 + ni * 8 + grp;
                b[ni][0] = Bs[kb + tig    ][n];
                b[ni][1] = Bs[kb + tig + 4][n];
            }
            #pragma unroll
            for (int mi = 0; mi < 2; mi++)
                #pragma unroll
                for (int ni = 0; ni < 8; ni++) {
                    asm volatile(
                        "mma.sync.aligned.m16n8k8.row.col.f32.tf32.tf32.f32 "
                        "{%0,%1,%2,%3}, {%4,%5,%6,%7}, {%8,%9}, {%0,%1,%2,%3};"
                        : "+f"(acc[mi][ni][0]), "+f"(acc[mi][ni][1]),
                          "+f"(acc[mi][ni][2]), "+f"(acc[mi][ni][3])
                        : "r"(a[mi][0]), "r"(a[mi][1]), "r"(a[mi][2]), "r"(a[mi][3]),
                          "r"(b[ni][0]), "r"(b[ni][1]));
                }
        }
        __syncthreads();
    }

    #pragma unroll
    for (int mi = 0; mi < 2; mi++) {
        int rbase = row0 + m0 + mi * 16 + grp;
        #pragma unroll
        for (int ni = 0; ni < 8; ni++) {
            int col = n0 + ni * 8 + 2 * tig;
            if (rbase < M) {
                float2 v0 = make_float2(acc[mi][ni][0], acc[mi][ni][1]);
                *(float2*)&C[(size_t)rbase * 128 + col] = v0;
            }
            if (rbase + 8 < M) {
                float2 v1 = make_float2(acc[mi][ni][2], acc[mi][ni][3]);
                *(float2*)&C[(size_t)(rbase + 8) * 128 + col] = v1;
            }
        }
    }
}

// ---------------- tf32 tensor GEMM2 + fused BN2 stats -----------------------
// t = relu(a*agg+c) @ W1  (M x 128 x 64); epilogue accumulates col sum/sumsq.
__global__ __launch_bounds__(256) void tgemm2_kernel(
    const float* __restrict__ A, const float* __restrict__ B, float* __restrict__ C,
    int M, const float* __restrict__ sc, const float* __restrict__ shf) {
    constexpr int BM = 128, BN = 64, BK = 32, K = 128;
    __shared__ uint32_t As[BM][BK + 4];
    __shared__ uint32_t Bs[BK][BN + 8];
    __shared__ float s_sc[K], s_sh[K];

    int tid = threadIdx.x;
    if (tid < K) { s_sc[tid] = sc[tid]; s_sh[tid] = shf[tid]; }

    int lane = tid & 31, wid = tid >> 5;
    int wr = wid & 3, wc = wid >> 2;        // warp tile: 32 rows x 32 cols
    int m0 = wr * 32, n0 = wc * 32;
    int row0 = blockIdx.x * BM;
    int grp = lane >> 2, tig = lane & 3;
    __syncthreads();

    float acc[2][4][4];
    #pragma unroll
    for (int i = 0; i < 2; i++)
        #pragma unroll
        for (int j = 0; j < 4; j++)
            #pragma unroll
            for (int r = 0; r < 4; r++) acc[i][j][r] = 0.f;

    for (int k0 = 0; k0 < K; k0 += BK) {
        #pragma unroll
        for (int p = 0; p < 4; p++) {
            int f = tid + p * 256;
            int r = f >> 3;
            int c4 = (f & 7) * 4;
            float4 v = make_float4(0.f, 0.f, 0.f, 0.f);
            if (row0 + r < M) v = *(const float4*)&A[(size_t)(row0 + r) * K + k0 + c4];
            int kb = k0 + c4;
            v.x = fmaxf(fmaf(v.x, s_sc[kb + 0], s_sh[kb + 0]), 0.f);
            v.y = fmaxf(fmaf(v.y, s_sc[kb + 1], s_sh[kb + 1]), 0.f);
            v.z = fmaxf(fmaf(v.z, s_sc[kb + 2], s_sh[kb + 2]), 0.f);
            v.w = fmaxf(fmaf(v.w, s_sc[kb + 3], s_sh[kb + 3]), 0.f);
            As[r][c4 + 0] = f_tf32(v.x); As[r][c4 + 1] = f_tf32(v.y);
            As[r][c4 + 2] = f_tf32(v.z); As[r][c4 + 3] = f_tf32(v.w);
        }
        #pragma unroll
        for (int p = 0; p < 2; p++) {
            int f = tid + p * 256;
            int kr = f >> 4;
            int c4 = (f & 15) * 4;
            float4 v = *(const float4*)&B[(size_t)(k0 + kr) * BN + c4];
            Bs[kr][c4 + 0] = f_tf32(v.x); Bs[kr][c4 + 1] = f_tf32(v.y);
            Bs[kr][c4 + 2] = f_tf32(v.z); Bs[kr][c4 + 3] = f_tf32(v.w);
        }
        __syncthreads();

        #pragma unroll
        for (int ks = 0; ks < BK / 8; ks++) {
            int kb = ks * 8;
            uint32_t a[2][4];
            #pragma unroll
            for (int mi = 0; mi < 2; mi++) {
                int r = m0 + mi * 16 + grp;
                a[mi][0] = As[r    ][kb + tig    ];
                a[mi][1] = As[r + 8][kb + tig    ];
                a[mi][2] = As[r    ][kb + tig + 4];
                a[mi][3] = As[r + 8][kb + tig + 4];
            }
            uint32_t b[4][2];
            #pragma unroll
            for (int ni = 0; ni < 4; ni++) {
                int n = n0 + ni * 8 + grp;
                b[ni][0] = Bs[kb + tig    ][n];
                b[ni][1] = Bs[kb + tig + 4][n];
            }
            #pragma unroll
            for (int mi = 0; mi < 2; mi++)
                #pragma unroll
                for (int ni = 0; ni < 4; ni++) {
                    asm volatile(
                        "mma.sync.aligned.m16n8k8.row.col.f32.tf32.tf32.f32 "
                        "{%0,%1,%2,%3}, {%4,%5,%6,%7}, {%8,%9}, {%0,%1,%2,%3};"
                        : "+f"(acc[mi][ni][0]), "+f"(acc[mi][ni][1]),
                          "+f"(acc[mi][ni][2]), "+f"(acc[mi][ni][3])
                        : "r"(a[mi][0]), "r"(a[mi][1]), "r"(a[mi][2]), "r"(a[mi][3]),
                          "r"(b[ni][0]), "r"(b[ni][1]));
                }
        }
        __syncthreads();
    }

    // write C
    #pragma unroll
    for (int mi = 0; mi < 2; mi++) {
        int rbase = row0 + m0 + mi * 16 + grp;
        #pragma unroll
        for (int ni = 0; ni < 4; ni++) {
            int col = n0 + ni * 8 + 2 * tig;
            if (rbase < M) {
                float2 v0 = make_float2(acc[mi][ni][0], acc[mi][ni][1]);
                *(float2*)&C[(size_t)rbase * BN + col] = v0;
            }
            if (rbase + 8 < M) {
                float2 v1 = make_float2(acc[mi][ni][2], acc[mi][ni][3]);
                *(float2*)&C[(size_t)(rbase + 8) * BN + col] = v1;
            }
        }
    }

    // fused BN2 stats: per-thread col partials over valid rows
    float csum[8], csq[8];
    #pragma unroll
    for (int ni = 0; ni < 4; ni++) {
        float s0 = 0.f, q0 = 0.f, s1 = 0.f, q1 = 0.f;
        #pragma unroll
        for (int mi = 0; mi < 2; mi++) {
            int r0 = row0 + m0 + mi * 16 + grp;
            if (r0 < M) {
                float v = acc[mi][ni][0]; s0 += v; q0 += v * v;
                v = acc[mi][ni][1]; s1 += v; q1 += v * v;
            }
            if (r0 + 8 < M) {
                float v = acc[mi][ni][2]; s0 += v; q0 += v * v;
                v = acc[mi][ni][3]; s1 += v; q1 += v * v;
            }
        }
        csum[ni * 2] = s0; csq[ni * 2] = q0;
        csum[ni * 2 + 1] = s1; csq[ni * 2 + 1] = q1;
    }
    // reduce across grp lanes (same tig share columns)
    #pragma unroll
    for (int o = 4; o < 32; o <<= 1) {
        #pragma unroll
        for (int j = 0; j < 8; j++) {
            csum[j] += __shfl_xor_sync(0xffffffffu, csum[j], o);
            csq[j]  += __shfl_xor_sync(0xffffffffu, csq[j], o);
        }
    }
    if (grp == 0) {
        #pragma unroll
        for (int j = 0; j < 8; j++) {
            int ni = j >> 1, half = j & 1;
            int col = n0 + ni * 8 + 2 * tig + half;
            atomicAdd(&g_sum2[col], csum[j]);
            atomicAdd(&g_sq2[col],  csq[j]);
        }
    }
}

// ---------------- SGEMM (R4 exact: single-buffer, BK=8) ---------------------
template <int N, int K, bool BNIN, bool BIAS>
__global__ __launch_bounds__(256) void sgemm_kernel(
    const float* __restrict__ A, const float* __restrict__ B, float* __restrict__ C,
    int M, const float* __restrict__ sc, const float* __restrict__ shf,
    const float* __restrict__ bias) {
    constexpr int BM = 128, BK = 8, TM = 8, TN = N / 16;
    __shared__ float As[BK][BM + 4];
    __shared__ float Bs[BK][N];
    __shared__ float s_sc[K], s_sh[K];

    int tid = threadIdx.x;
    if (BNIN) {
        for (int i = tid; i < K; i += 256) { s_sc[i] = sc[i]; s_sh[i] = shf[i]; }
    }
    __syncthreads();

    int tx = tid & 15, ty = tid >> 4;
    int row0 = blockIdx.x * BM;

    float acc[TM][TN];
    #pragma unroll
    for (int i = 0; i < TM; i++)
        #pragma unroll
        for (int j = 0; j < TN; j++) acc[i][j] = 0.f;

    int ar = tid >> 1;
    int ak = (tid & 1) * 4;
    int arow = row0 + ar;
    bool avalid = (arow < M);

    for (int k0 = 0; k0 < K; k0 += BK) {
        float4 av = make_float4(0.f, 0.f, 0.f, 0.f);
        if (avalid) av = *(const float4*)&A[(size_t)arow * K + k0 + ak];
        if (BNIN) {
            av.x = fmaxf(fmaf(av.x, s_sc[k0 + ak + 0], s_sh[k0 + ak + 0]), 0.f);
            av.y = fmaxf(fmaf(av.y, s_sc[k0 + ak + 1], s_sh[k0 + ak + 1]), 0.f);
            av.z = fmaxf(fmaf(av.z, s_sc[k0 + ak + 2], s_sh[k0 + ak + 2]), 0.f);
            av.w = fmaxf(fmaf(av.w, s_sc[k0 + ak + 3], s_sh[k0 + ak + 3]), 0.f);
        }
        As[ak + 0][ar] = av.x; As[ak + 1][ar] = av.y;
        As[ak + 2][ar] = av.z; As[ak + 3][ar] = av.w;

        #pragma unroll
        for (int i = tid; i < BK * N / 4; i += 256) {
            int kr = i / (N / 4);
            int c4 = (i % (N / 4)) * 4;
            *(float4*)&Bs[kr][c4] = *(const float4*)&B[(size_t)(k0 + kr) * N + c4];
        }
        __syncthreads();

        #pragma unroll
        for (int kk = 0; kk < BK; kk++) {
            float a[TM], b[TN];
            *(float4*)&a[0] = *(const float4*)&As[kk][ty * TM];
            *(float4*)&a[4] = *(const float4*)&As[kk][ty * TM + 4];
            #pragma unroll
            for (int j = 0; j < TN; j += 4)
                *(float4*)&b[j] = *(const float4*)&Bs[kk][tx * TN + j];
            #pragma unroll
            for (int i = 0; i < TM; i++)
                #pragma unroll
                for (int j = 0; j < TN; j++)
                    acc[i][j] = fmaf(a[i], b[j], acc[i][j]);
        }
        __syncthreads();
    }

    float bj[TN];
    if (BIAS) {
        #pragma unroll
        for (int j = 0; j < TN; j++) bj[j] = bias[tx * TN + j];
    }
    #pragma unroll
    for (int i = 0; i < TM; i++) {
        int grow = row0 + ty * TM + i;
        if (grow < M) {
            #pragma unroll
            for (int j = 0; j < TN; j += 4) {
                float4 v;
                v.x = acc[i][j]; v.y = acc[i][j + 1];
                v.z = acc[i][j + 2]; v.w = acc[i][j + 3];
                if (BIAS) { v.x += bj[j]; v.y += bj[j + 1]; v.z += bj[j + 2]; v.w += bj[j + 3]; }
                *(float4*)&C[(size_t)grow * N + tx * TN + j] = v;
            }
        }
    }
}

// ---------------- launch ----------------------------------------------------
extern "C" void kernel_launch(void* const* d_in, const int* in_sizes, int n_in,
                              void* d_out, int out_size) {
    const float* x     = (const float*)d_in[0];
    const int*   ei    = (const int*)d_in[1];
    const float* W_gcn = (const float*)d_in[2];
    // d_in[3] = b_gcn : exactly absorbed by BN1 (mean-subtraction) -> unused
    const float* bn_g  = (const float*)d_in[4];
    const float* bn_b  = (const float*)d_in[5];
    const float* W1    = (const float*)d_in[6];
    // d_in[7] = b1    : exactly absorbed by BN2 -> unused
    const float* mg    = (const float*)d_in[8];
    const float* mb    = (const float*)d_in[9];
    const float* W2    = (const float*)d_in[10];
    const float* b2    = (const float*)d_in[11];
    float* out = (float*)d_out;

    int M = in_sizes[0] / FIN;
    int E = in_sizes[1] / 2;
    const int* src = ei;
    const int* dst = ei + E;

    void *p_h, *p_agg, *p_t, *p_sum1, *p_sq1, *p_a1, *p_c1, *p_sum2, *p_sq2, *p_a2, *p_c2;
    cudaGetSymbolAddress(&p_h, g_h);
    cudaGetSymbolAddress(&p_agg, g_agg);
    cudaGetSymbolAddress(&p_t, g_t);
    cudaGetSymbolAddress(&p_sum1, g_sum1);
    cudaGetSymbolAddress(&p_sq1, g_sq1);
    cudaGetSymbolAddress(&p_a1, g_a1);
    cudaGetSymbolAddress(&p_c1, g_c1);
    cudaGetSymbolAddress(&p_sum2, g_sum2);
    cudaGetSymbolAddress(&p_sq2, g_sq2);
    cudaGetSymbolAddress(&p_a2, g_a2);
    cudaGetSymbolAddress(&p_c2, g_c2);

    // index machinery (4 kernels instead of 7)
    zero_kernel<<<256, 256>>>(M);
    deg_kernel<<<(E + 255) / 256, 256>>>(dst, E, M);
    alloc_kernel<<<(M + 255) / 256, 256>>>(M);
    fill_kernel<<<(E + 255) / 256, 256>>>(src, dst, E, M);

    // GEMM1 (tf32 tensor cores): h = x @ W_gcn
    tgemm1_kernel<<<(M + 127) / 128, 256>>>(x, W_gcn, (float*)p_h, M);

    // CSR gather
    gather_kernel<<<(M * 32 + 255) / 256, 256>>>(M);

    // BN1 stats
    stats_kernel<FIN><<<1024, 256>>>((const float*)p_agg, M, (float*)p_sum1, (float*)p_sq1);
    finalize_kernel<FIN><<<1, 128>>>((const float*)p_sum1, (const float*)p_sq1,
                                     bn_g, bn_b, M, (float*)p_a1, (float*)p_c1);

    // GEMM2 (tf32 + fused BN2 stats): t = relu(BN1(agg)) @ W1
    tgemm2_kernel<<<(M + 127) / 128, 256>>>(
        (const float*)p_agg, W1, (float*)p_t, M,
        (const float*)p_a1, (const float*)p_c1);

    finalize_kernel<FOUT><<<1, 64>>>((const float*)p_sum2, (const float*)p_sq2,
                                     mg, mb, M, (float*)p_a2, (float*)p_c2);

    // GEMM3 (exact fp32): out = relu(BN2(t)) @ W2 + b2
    sgemm_kernel<FOUT, FOUT, true, true><<<(M + 127) / 128, 256>>>(
        (const float*)p_t, W2, out, M,
        (const float*)p_a2, (const float*)p_c2, b2);
}

// round 11
// speedup vs baseline: 1.0503x; 1.0503x over previous
#include <cuda_runtime.h>
#include <cstdint>

#define NNODES 100000
#define NEDGES 640000
#define FIN 128
#define FOUT 64
#define BN_EPS 1e-5f

// ---------------- scratch (static device globals; no runtime allocation) ----
__device__ float g_h[(size_t)NNODES * FIN];     // x @ W_gcn
__device__ float g_agg[(size_t)NNODES * FIN];   // aggregated messages
__device__ float g_t[(size_t)NNODES * FOUT];    // hidden after GEMM2
__device__ int   g_degi[NNODES];
__device__ float g_dinv[NNODES];
__device__ int   g_off[NNODES + 1];
__device__ int   g_cursor[NNODES];
__device__ int   g_alloc;
__device__ int   g_elist[NEDGES];
__device__ float g_sum1[FIN], g_sq1[FIN], g_a1[FIN], g_c1[FIN];
__device__ float g_sum2[FOUT], g_sq2[FOUT], g_a2[FOUT], g_c2[FOUT];

// ---------------- zero ------------------------------------------------------
__global__ void zero_kernel(int M) {
    int i = blockIdx.x * blockDim.x + threadIdx.x;
    for (int j = i; j < M; j += gridDim.x * blockDim.x) g_degi[j] = 0;
    if (i < FIN)  { g_sum1[i] = 0.f; g_sq1[i] = 0.f; }
    if (i < FOUT) { g_sum2[i] = 0.f; g_sq2[i] = 0.f; }
    if (i == 0) g_alloc = 0;
}

// ---------------- in-degree count -------------------------------------------
__global__ void deg_kernel(const int* __restrict__ dst, int E, int M) {
    int e = blockIdx.x * blockDim.x + threadIdx.x;
    if (e < E) {
        int d = dst[e];
        if ((unsigned)d < (unsigned)M) atomicAdd(&g_degi[d], 1);
    }
}

// ---------------- CSR segment allocation (warp-aggregated) ------------------
// Replaces the 3-kernel prefix scan: segment order is irrelevant, only
// per-node contiguity matters. One atomicAdd per warp.
__global__ void alloc_kernel(int M) {
    int i = blockIdx.x * blockDim.x + threadIdx.x;
    int lane = threadIdx.x & 31;
    int deg = 0;
    if (i < M) deg = g_degi[i];
    int incl = deg;
    #pragma unroll
    for (int o = 1; o < 32; o <<= 1) {
        int v = __shfl_up_sync(0xffffffffu, incl, o);
        if (lane >= o) incl += v;
    }
    int total = __shfl_sync(0xffffffffu, incl, 31);
    int base = 0;
    if (lane == 0) base = atomicAdd(&g_alloc, total);
    base = __shfl_sync(0xffffffffu, base, 0);
    if (i < M) {
        int o = base + incl - deg;
        g_off[i] = o;
        g_cursor[i] = o;
        g_dinv[i] = rsqrtf((float)deg + 1.0f);  // +1 = self loop
    }
}

// ---------------- edge-list fill --------------------------------------------
__global__ void fill_kernel(const int* __restrict__ src, const int* __restrict__ dst,
                            int E, int M) {
    int e = blockIdx.x * blockDim.x + threadIdx.x;
    if (e < E) {
        int s = src[e];
        int d = dst[e];
        if ((unsigned)s < (unsigned)M && (unsigned)d < (unsigned)M) {
            int p = atomicAdd(&g_cursor[d], 1);
            g_elist[p] = s;
        }
    }
}

// ---------------- gather (R4 exact) -----------------------------------------
__global__ void gather_kernel(int M) {
    int warp = (blockIdx.x * blockDim.x + threadIdx.x) >> 5;
    int lane = threadIdx.x & 31;
    if (warp >= M) return;
    int d = warp;
    int e0 = g_off[d];
    int e1 = g_cursor[d];
    float4 acc = make_float4(0.f, 0.f, 0.f, 0.f);
    for (int e = e0; e < e1; e++) {
        int s = g_elist[e];
        float ws = g_dinv[s];
        float4 v = *(const float4*)&g_h[(size_t)s * FIN + lane * 4];
        acc.x = fmaf(v.x, ws, acc.x);
        acc.y = fmaf(v.y, ws, acc.y);
        acc.z = fmaf(v.z, ws, acc.z);
        acc.w = fmaf(v.w, ws, acc.w);
    }
    float wd = g_dinv[d];
    float4 vs = *(const float4*)&g_h[(size_t)d * FIN + lane * 4];
    float4 o;
    o.x = wd * acc.x + wd * wd * vs.x;
    o.y = wd * acc.y + wd * wd * vs.y;
    o.z = wd * acc.z + wd * wd * vs.z;
    o.w = wd * acc.w + wd * wd * vs.w;
    *(float4*)&g_agg[(size_t)d * FIN + lane * 4] = o;
}

// ---------------- per-column sum / sumsq ------------------------------------
template <int F>
__global__ void stats_kernel(const float* __restrict__ X, int M,
                             float* __restrict__ sum, float* __restrict__ sq) {
    constexpr int RP = 256 / F;
    int col  = threadIdx.x % F;
    int rsub = threadIdx.x / F;
    float s = 0.f, q = 0.f;
    for (int r = blockIdx.x * RP + rsub; r < M; r += gridDim.x * RP) {
        float v = X[(size_t)r * F + col];
        s += v; q += v * v;
    }
    __shared__ float sh[256];
    sh[threadIdx.x] = s; __syncthreads();
    if (rsub == 0) {
        #pragma unroll
        for (int k = 1; k < RP; k++) s += sh[k * F + col];
    }
    __syncthreads();
    sh[threadIdx.x] = q; __syncthreads();
    if (rsub == 0) {
        #pragma unroll
        for (int k = 1; k < RP; k++) q += sh[k * F + col];
        atomicAdd(&sum[col], s);
        atomicAdd(&sq[col],  q);
    }
}

template <int F>
__global__ void finalize_kernel(const float* __restrict__ sum, const float* __restrict__ sq,
                                const float* __restrict__ gamma, const float* __restrict__ beta,
                                int M, float* __restrict__ a, float* __restrict__ c) {
    int i = threadIdx.x;
    if (i < F) {
        float mean = sum[i] / (float)M;
        float var  = sq[i] / (float)M - mean * mean;
        float s = gamma[i] * rsqrtf(var + BN_EPS);
        a[i] = s;
        c[i] = beta[i] - mean * s;
    }
}

// ---------------- tf32 helpers ----------------------------------------------
__device__ __forceinline__ uint32_t f_tf32(float x) {
    uint32_t y;
    asm("cvt.rna.tf32.f32 %0, %1;" : "=r"(y) : "f"(x));
    return y;
}

// ---------------- tf32 tensor GEMM1: h = x @ W  (M x 128 x 128) -------------
__global__ __launch_bounds__(256) void tgemm1_kernel(
    const float* __restrict__ A, const float* __restrict__ B, float* __restrict__ C, int M) {
    constexpr int BM = 128, BN = 128, BK = 32;
    __shared__ uint32_t As[BM][BK + 4];
    __shared__ uint32_t Bs[BK][BN + 8];

    int tid = threadIdx.x;
    int lane = tid & 31, wid = tid >> 5;
    int wr = wid & 3, wc = wid >> 2;        // warp tile: 32 rows x 64 cols
    int m0 = wr * 32, n0 = wc * 64;
    int row0 = blockIdx.x * BM;
    int grp = lane >> 2, tig = lane & 3;

    float acc[2][8][4];
    #pragma unroll
    for (int i = 0; i < 2; i++)
        #pragma unroll
        for (int j = 0; j < 8; j++)
            #pragma unroll
            for (int r = 0; r < 4; r++) acc[i][j][r] = 0.f;

    for (int k0 = 0; k0 < 128; k0 += BK) {
        #pragma unroll
        for (int p = 0; p < 4; p++) {
            int f = tid + p * 256;
            int r = f >> 3;
            int c4 = (f & 7) * 4;
            float4 v = make_float4(0.f, 0.f, 0.f, 0.f);
            if (row0 + r < M) v = *(const float4*)&A[(size_t)(row0 + r) * 128 + k0 + c4];
            As[r][c4 + 0] = f_tf32(v.x); As[r][c4 + 1] = f_tf32(v.y);
            As[r][c4 + 2] = f_tf32(v.z); As[r][c4 + 3] = f_tf32(v.w);
        }
        #pragma unroll
        for (int p = 0; p < 4; p++) {
            int f = tid + p * 256;
            int kr = f >> 5;
            int c4 = (f & 31) * 4;
            float4 v = *(const float4*)&B[(size_t)(k0 + kr) * 128 + c4];
            Bs[kr][c4 + 0] = f_tf32(v.x); Bs[kr][c4 + 1] = f_tf32(v.y);
            Bs[kr][c4 + 2] = f_tf32(v.z); Bs[kr][c4 + 3] = f_tf32(v.w);
        }
        __syncthreads();

        #pragma unroll
        for (int ks = 0; ks < BK / 8; ks++) {
            int kb = ks * 8;
            uint32_t a[2][4];
            #pragma unroll
            for (int mi = 0; mi < 2; mi++) {
                int r = m0 + mi * 16 + grp;
                a[mi][0] = As[r    ][kb + tig    ];
                a[mi][1] = As[r + 8][kb + tig    ];
                a[mi][2] = As[r    ][kb + tig + 4];
                a[mi][3] = As[r + 8][kb + tig + 4];
            }
            uint32_t b[8][2];
            #pragma unroll
            for (int ni = 0; ni < 8; ni++) {
                int n = n0 + ni * 8 + grp;
                b[ni][0] = Bs[kb + tig    ][n];
                b[ni][1] = Bs[kb + tig + 4][n];
            }
            #pragma unroll
            for (int mi = 0; mi < 2; mi++)
                #pragma unroll
                for (int ni = 0; ni < 8; ni++) {
                    asm volatile(
                        "mma.sync.aligned.m16n8k8.row.col.f32.tf32.tf32.f32 "
                        "{%0,%1,%2,%3}, {%4,%5,%6,%7}, {%8,%9}, {%0,%1,%2,%3};"
                        : "+f"(acc[mi][ni][0]), "+f"(acc[mi][ni][1]),
                          "+f"(acc[mi][ni][2]), "+f"(acc[mi][ni][3])
                        : "r"(a[mi][0]), "r"(a[mi][1]), "r"(a[mi][2]), "r"(a[mi][3]),
                          "r"(b[ni][0]), "r"(b[ni][1]));
                }
        }
        __syncthreads();
    }

    #pragma unroll
    for (int mi = 0; mi < 2; mi++) {
        int rbase = row0 + m0 + mi * 16 + grp;
        #pragma unroll
        for (int ni = 0; ni < 8; ni++) {
            int col = n0 + ni * 8 + 2 * tig;
            if (rbase < M) {
                float2 v0 = make_float2(acc[mi][ni][0], acc[mi][ni][1]);
                *(float2*)&C[(size_t)rbase * 128 + col] = v0;
            }
            if (rbase + 8 < M) {
                float2 v1 = make_float2(acc[mi][ni][2], acc[mi][ni][3]);
                *(float2*)&C[(size_t)(rbase + 8) * 128 + col] = v1;
            }
        }
    }
}

// ---------------- tf32 tensor GEMM2: t = relu(a*agg+c) @ W1 (M x 128 x 64) --
__global__ __launch_bounds__(256) void tgemm2_kernel(
    const float* __restrict__ A, const float* __restrict__ B, float* __restrict__ C,
    int M, const float* __restrict__ sc, const float* __restrict__ shf) {
    constexpr int BM = 128, BN = 64, BK = 32, K = 128;
    __shared__ uint32_t As[BM][BK + 4];
    __shared__ uint32_t Bs[BK][BN + 8];
    __shared__ float s_sc[K], s_sh[K];

    int tid = threadIdx.x;
    if (tid < K) { s_sc[tid] = sc[tid]; s_sh[tid] = shf[tid]; }

    int lane = tid & 31, wid = tid >> 5;
    int wr = wid & 3, wc = wid >> 2;        // warp tile: 32 rows x 32 cols
    int m0 = wr * 32, n0 = wc * 32;
    int row0 = blockIdx.x * BM;
    int grp = lane >> 2, tig = lane & 3;
    __syncthreads();

    float acc[2][4][4];
    #pragma unroll
    for (int i = 0; i < 2; i++)
        #pragma unroll
        for (int j = 0; j < 4; j++)
            #pragma unroll
            for (int r = 0; r < 4; r++) acc[i][j][r] = 0.f;

    for (int k0 = 0; k0 < K; k0 += BK) {
        #pragma unroll
        for (int p = 0; p < 4; p++) {
            int f = tid + p * 256;
            int r = f >> 3;
            int c4 = (f & 7) * 4;
            float4 v = make_float4(0.f, 0.f, 0.f, 0.f);
            if (row0 + r < M) v = *(const float4*)&A[(size_t)(row0 + r) * K + k0 + c4];
            int kb = k0 + c4;
            v.x = fmaxf(fmaf(v.x, s_sc[kb + 0], s_sh[kb + 0]), 0.f);
            v.y = fmaxf(fmaf(v.y, s_sc[kb + 1], s_sh[kb + 1]), 0.f);
            v.z = fmaxf(fmaf(v.z, s_sc[kb + 2], s_sh[kb + 2]), 0.f);
            v.w = fmaxf(fmaf(v.w, s_sc[kb + 3], s_sh[kb + 3]), 0.f);
            As[r][c4 + 0] = f_tf32(v.x); As[r][c4 + 1] = f_tf32(v.y);
            As[r][c4 + 2] = f_tf32(v.z); As[r][c4 + 3] = f_tf32(v.w);
        }
        #pragma unroll
        for (int p = 0; p < 2; p++) {
            int f = tid + p * 256;
            int kr = f >> 4;
            int c4 = (f & 15) * 4;
            float4 v = *(const float4*)&B[(size_t)(k0 + kr) * BN + c4];
            Bs[kr][c4 + 0] = f_tf32(v.x); Bs[kr][c4 + 1] = f_tf32(v.y);
            Bs[kr][c4 + 2] = f_tf32(v.z); Bs[kr][c4 + 3] = f_tf32(v.w);
        }
        __syncthreads();

        #pragma unroll
        for (int ks = 0; ks < BK / 8; ks++) {
            int kb = ks * 8;
            uint32_t a[2][4];
            #pragma unroll
            for (int mi = 0; mi < 2; mi++) {
                int r = m0 + mi * 16 + grp;
                a[mi][0] = As[r    ][kb + tig    ];
                a[mi][1] = As[r + 8][kb + tig    ];
                a[mi][2] = As[r    ][kb + tig + 4];
                a[mi][3] = As[r + 8][kb + tig + 4];
            }
            uint32_t b[4][2];
            #pragma unroll
            for (int ni = 0; ni < 4; ni++) {
                int n = n0 + ni * 8 + grp;
                b[ni][0] = Bs[kb + tig    ][n];
                b[ni][1] = Bs[kb + tig + 4][n];
            }
            #pragma unroll
            for (int mi = 0; mi < 2; mi++)
                #pragma unroll
                for (int ni = 0; ni < 4; ni++) {
                    asm volatile(
                        "mma.sync.aligned.m16n8k8.row.col.f32.tf32.tf32.f32 "
                        "{%0,%1,%2,%3}, {%4,%5,%6,%7}, {%8,%9}, {%0,%1,%2,%3};"
                        : "+f"(acc[mi][ni][0]), "+f"(acc[mi][ni][1]),
                          "+f"(acc[mi][ni][2]), "+f"(acc[mi][ni][3])
                        : "r"(a[mi][0]), "r"(a[mi][1]), "r"(a[mi][2]), "r"(a[mi][3]),
                          "r"(b[ni][0]), "r"(b[ni][1]));
                }
        }
        __syncthreads();
    }

    #pragma unroll
    for (int mi = 0; mi < 2; mi++) {
        int rbase = row0 + m0 + mi * 16 + grp;
        #pragma unroll
        for (int ni = 0; ni < 4; ni++) {
            int col = n0 + ni * 8 + 2 * tig;
            if (rbase < M) {
                float2 v0 = make_float2(acc[mi][ni][0], acc[mi][ni][1]);
                *(float2*)&C[(size_t)rbase * BN + col] = v0;
            }
            if (rbase + 8 < M) {
                float2 v1 = make_float2(acc[mi][ni][2], acc[mi][ni][3]);
                *(float2*)&C[(size_t)(rbase + 8) * BN + col] = v1;
            }
        }
    }
}

// ---------------- SGEMM (R4 exact: single-buffer, BK=8) ---------------------
template <int N, int K, bool BNIN, bool BIAS>
__global__ __launch_bounds__(256) void sgemm_kernel(
    const float* __restrict__ A, const float* __restrict__ B, float* __restrict__ C,
    int M, const float* __restrict__ sc, const float* __restrict__ shf,
    const float* __restrict__ bias) {
    constexpr int BM = 128, BK = 8, TM = 8, TN = N / 16;
    __shared__ float As[BK][BM + 4];
    __shared__ float Bs[BK][N];
    __shared__ float s_sc[K], s_sh[K];

    int tid = threadIdx.x;
    if (BNIN) {
        for (int i = tid; i < K; i += 256) { s_sc[i] = sc[i]; s_sh[i] = shf[i]; }
    }
    __syncthreads();

    int tx = tid & 15, ty = tid >> 4;
    int row0 = blockIdx.x * BM;

    float acc[TM][TN];
    #pragma unroll
    for (int i = 0; i < TM; i++)
        #pragma unroll
        for (int j = 0; j < TN; j++) acc[i][j] = 0.f;

    int ar = tid >> 1;
    int ak = (tid & 1) * 4;
    int arow = row0 + ar;
    bool avalid = (arow < M);

    for (int k0 = 0; k0 < K; k0 += BK) {
        float4 av = make_float4(0.f, 0.f, 0.f, 0.f);
        if (avalid) av = *(const float4*)&A[(size_t)arow * K + k0 + ak];
        if (BNIN) {
            av.x = fmaxf(fmaf(av.x, s_sc[k0 + ak + 0], s_sh[k0 + ak + 0]), 0.f);
            av.y = fmaxf(fmaf(av.y, s_sc[k0 + ak + 1], s_sh[k0 + ak + 1]), 0.f);
            av.z = fmaxf(fmaf(av.z, s_sc[k0 + ak + 2], s_sh[k0 + ak + 2]), 0.f);
            av.w = fmaxf(fmaf(av.w, s_sc[k0 + ak + 3], s_sh[k0 + ak + 3]), 0.f);
        }
        As[ak + 0][ar] = av.x; As[ak + 1][ar] = av.y;
        As[ak + 2][ar] = av.z; As[ak + 3][ar] = av.w;

        #pragma unroll
        for (int i = tid; i < BK * N / 4; i += 256) {
            int kr = i / (N / 4);
            int c4 = (i % (N / 4)) * 4;
            *(float4*)&Bs[kr][c4] = *(const float4*)&B[(size_t)(k0 + kr) * N + c4];
        }
        __syncthreads();

        #pragma unroll
        for (int kk = 0; kk < BK; kk++) {
            float a[TM], b[TN];
            *(float4*)&a[0] = *(const float4*)&As[kk][ty * TM];
            *(float4*)&a[4] = *(const float4*)&As[kk][ty * TM + 4];
            #pragma unroll
            for (int j = 0; j < TN; j += 4)
                *(float4*)&b[j] = *(const float4*)&Bs[kk][tx * TN + j];
            #pragma unroll
            for (int i = 0; i < TM; i++)
                #pragma unroll
                for (int j = 0; j < TN; j++)
                    acc[i][j] = fmaf(a[i], b[j], acc[i][j]);
        }
        __syncthreads();
    }

    float bj[TN];
    if (BIAS) {
        #pragma unroll
        for (int j = 0; j < TN; j++) bj[j] = bias[tx * TN + j];
    }
    #pragma unroll
    for (int i = 0; i < TM; i++) {
        int grow = row0 + ty * TM + i;
        if (grow < M) {
            #pragma unroll
            for (int j = 0; j < TN; j += 4) {
                float4 v;
                v.x = acc[i][j]; v.y = acc[i][j + 1];
                v.z = acc[i][j + 2]; v.w = acc[i][j + 3];
                if (BIAS) { v.x += bj[j]; v.y += bj[j + 1]; v.z += bj[j + 2]; v.w += bj[j + 3]; }
                *(float4*)&C[(size_t)grow * N + tx * TN + j] = v;
            }
        }
    }
}

// ---------------- launch ----------------------------------------------------
extern "C" void kernel_launch(void* const* d_in, const int* in_sizes, int n_in,
                              void* d_out, int out_size) {
    const float* x     = (const float*)d_in[0];
    const int*   ei    = (const int*)d_in[1];
    const float* W_gcn = (const float*)d_in[2];
    // d_in[3] = b_gcn : exactly absorbed by BN1 (mean-subtraction) -> unused
    const float* bn_g  = (const float*)d_in[4];
    const float* bn_b  = (const float*)d_in[5];
    const float* W1    = (const float*)d_in[6];
    // d_in[7] = b1    : exactly absorbed by BN2 -> unused
    const float* mg    = (const float*)d_in[8];
    const float* mb    = (const float*)d_in[9];
    const float* W2    = (const float*)d_in[10];
    const float* b2    = (const float*)d_in[11];
    float* out = (float*)d_out;

    int M = in_sizes[0] / FIN;
    int E = in_sizes[1] / 2;
    const int* src = ei;
    const int* dst = ei + E;

    void *p_h, *p_agg, *p_t, *p_sum1, *p_sq1, *p_a1, *p_c1, *p_sum2, *p_sq2, *p_a2, *p_c2;
    cudaGetSymbolAddress(&p_h, g_h);
    cudaGetSymbolAddress(&p_agg, g_agg);
    cudaGetSymbolAddress(&p_t, g_t);
    cudaGetSymbolAddress(&p_sum1, g_sum1);
    cudaGetSymbolAddress(&p_sq1, g_sq1);
    cudaGetSymbolAddress(&p_a1, g_a1);
    cudaGetSymbolAddress(&p_c1, g_c1);
    cudaGetSymbolAddress(&p_sum2, g_sum2);
    cudaGetSymbolAddress(&p_sq2, g_sq2);
    cudaGetSymbolAddress(&p_a2, g_a2);
    cudaGetSymbolAddress(&p_c2, g_c2);

    // index machinery (4 kernels)
    zero_kernel<<<256, 256>>>(M);
    deg_kernel<<<(E + 255) / 256, 256>>>(dst, E, M);
    alloc_kernel<<<(M + 255) / 256, 256>>>(M);
    fill_kernel<<<(E + 255) / 256, 256>>>(src, dst, E, M);

    // GEMM1 (tf32 tensor cores): h = x @ W_gcn
    tgemm1_kernel<<<(M + 127) / 128, 256>>>(x, W_gcn, (float*)p_h, M);

    // CSR gather
    gather_kernel<<<(M * 32 + 255) / 256, 256>>>(M);

    // BN1 stats
    stats_kernel<FIN><<<1024, 256>>>((const float*)p_agg, M, (float*)p_sum1, (float*)p_sq1);
    finalize_kernel<FIN><<<1, 128>>>((const float*)p_sum1, (const float*)p_sq1,
                                     bn_g, bn_b, M, (float*)p_a1, (float*)p_c1);

    // GEMM2 (tf32 tensor cores): t = relu(BN1(agg)) @ W1  (b1 absorbed by BN2)
    tgemm2_kernel<<<(M + 127) / 128, 256>>>(
        (const float*)p_agg, W1, (float*)p_t, M,
        (const float*)p_a1, (const float*)p_c1);

    // BN2 stats
    stats_kernel<FOUT><<<1024, 256>>>((const float*)p_t, M, (float*)p_sum2, (float*)p_sq2);
    finalize_kernel<FOUT><<<1, 64>>>((const float*)p_sum2, (const float*)p_sq2,
                                     mg, mb, M, (float*)p_a2, (float*)p_c2);

    // GEMM3 (exact fp32): out = relu(BN2(t)) @ W2 + b2
    sgemm_kernel<FOUT, FOUT, true, true><<<(M + 127) / 128, 256>>>(
        (const float*)p_t, W2, out, M,
        (const float*)p_a2, (const float*)p_c2, b2);
}

// round 12
// speedup vs baseline: 1.0716x; 1.0203x over previous
#include <cuda_runtime.h>
#include <cstdint>

#define NNODES 100000
#define NEDGES 640000
#define FIN 128
#define FOUT 64
#define BN_EPS 1e-5f

// ---------------- scratch (static device globals; no runtime allocation) ----
__device__ float g_h[(size_t)NNODES * FIN];     // x @ W_gcn
__device__ float g_agg[(size_t)NNODES * FIN];   // aggregated messages
__device__ float g_t[(size_t)NNODES * FOUT];    // hidden after GEMM2
__device__ int   g_degi[NNODES];
__device__ float g_dinv[NNODES];
__device__ int   g_off[NNODES + 1];
__device__ int   g_cursor[NNODES];
__device__ int   g_alloc;
__device__ int   g_elist[NEDGES];
__device__ float g_sum1[FIN], g_sq1[FIN], g_a1[FIN], g_c1[FIN];
__device__ float g_sum2[FOUT], g_sq2[FOUT], g_a2[FOUT], g_c2[FOUT];

// ---------------- zero ------------------------------------------------------
__global__ void zero_kernel(int M) {
    int i = blockIdx.x * blockDim.x + threadIdx.x;
    for (int j = i; j < M; j += gridDim.x * blockDim.x) g_degi[j] = 0;
    if (i < FIN)  { g_sum1[i] = 0.f; g_sq1[i] = 0.f; }
    if (i < FOUT) { g_sum2[i] = 0.f; g_sq2[i] = 0.f; }
    if (i == 0) g_alloc = 0;
}

// ---------------- in-degree count -------------------------------------------
__global__ void deg_kernel(const int* __restrict__ dst, int E, int M) {
    int e = blockIdx.x * blockDim.x + threadIdx.x;
    if (e < E) {
        int d = dst[e];
        if ((unsigned)d < (unsigned)M) atomicAdd(&g_degi[d], 1);
    }
}

// ---------------- CSR segment allocation (warp-aggregated) ------------------
__global__ void alloc_kernel(int M) {
    int i = blockIdx.x * blockDim.x + threadIdx.x;
    int lane = threadIdx.x & 31;
    int deg = 0;
    if (i < M) deg = g_degi[i];
    int incl = deg;
    #pragma unroll
    for (int o = 1; o < 32; o <<= 1) {
        int v = __shfl_up_sync(0xffffffffu, incl, o);
        if (lane >= o) incl += v;
    }
    int total = __shfl_sync(0xffffffffu, incl, 31);
    int base = 0;
    if (lane == 0) base = atomicAdd(&g_alloc, total);
    base = __shfl_sync(0xffffffffu, base, 0);
    if (i < M) {
        int o = base + incl - deg;
        g_off[i] = o;
        g_cursor[i] = o;
        g_dinv[i] = rsqrtf((float)deg + 1.0f);  // +1 = self loop
    }
}

// ---------------- edge-list fill --------------------------------------------
__global__ void fill_kernel(const int* __restrict__ src, const int* __restrict__ dst,
                            int E, int M) {
    int e = blockIdx.x * blockDim.x + threadIdx.x;
    if (e < E) {
        int s = src[e];
        int d = dst[e];
        if ((unsigned)s < (unsigned)M && (unsigned)d < (unsigned)M) {
            int p = atomicAdd(&g_cursor[d], 1);
            g_elist[p] = s;
        }
    }
}

// ---------------- gather (R4 exact) -----------------------------------------
__global__ void gather_kernel(int M) {
    int warp = (blockIdx.x * blockDim.x + threadIdx.x) >> 5;
    int lane = threadIdx.x & 31;
    if (warp >= M) return;
    int d = warp;
    int e0 = g_off[d];
    int e1 = g_cursor[d];
    float4 acc = make_float4(0.f, 0.f, 0.f, 0.f);
    for (int e = e0; e < e1; e++) {
        int s = g_elist[e];
        float ws = g_dinv[s];
        float4 v = *(const float4*)&g_h[(size_t)s * FIN + lane * 4];
        acc.x = fmaf(v.x, ws, acc.x);
        acc.y = fmaf(v.y, ws, acc.y);
        acc.z = fmaf(v.z, ws, acc.z);
        acc.w = fmaf(v.w, ws, acc.w);
    }
    float wd = g_dinv[d];
    float4 vs = *(const float4*)&g_h[(size_t)d * FIN + lane * 4];
    float4 o;
    o.x = wd * acc.x + wd * wd * vs.x;
    o.y = wd * acc.y + wd * wd * vs.y;
    o.z = wd * acc.z + wd * wd * vs.z;
    o.w = wd * acc.w + wd * wd * vs.w;
    *(float4*)&g_agg[(size_t)d * FIN + lane * 4] = o;
}

// ---------------- per-column sum / sumsq ------------------------------------
template <int F>
__global__ void stats_kernel(const float* __restrict__ X, int M,
                             float* __restrict__ sum, float* __restrict__ sq) {
    constexpr int RP = 256 / F;
    int col  = threadIdx.x % F;
    int rsub = threadIdx.x / F;
    float s = 0.f, q = 0.f;
    for (int r = blockIdx.x * RP + rsub; r < M; r += gridDim.x * RP) {
        float v = X[(size_t)r * F + col];
        s += v; q += v * v;
    }
    __shared__ float sh[256];
    sh[threadIdx.x] = s; __syncthreads();
    if (rsub == 0) {
        #pragma unroll
        for (int k = 1; k < RP; k++) s += sh[k * F + col];
    }
    __syncthreads();
    sh[threadIdx.x] = q; __syncthreads();
    if (rsub == 0) {
        #pragma unroll
        for (int k = 1; k < RP; k++) q += sh[k * F + col];
        atomicAdd(&sum[col], s);
        atomicAdd(&sq[col],  q);
    }
}

template <int F>
__global__ void finalize_kernel(const float* __restrict__ sum, const float* __restrict__ sq,
                                const float* __restrict__ gamma, const float* __restrict__ beta,
                                int M, float* __restrict__ a, float* __restrict__ c) {
    int i = threadIdx.x;
    if (i < F) {
        float mean = sum[i] / (float)M;
        float var  = sq[i] / (float)M - mean * mean;
        float s = gamma[i] * rsqrtf(var + BN_EPS);
        a[i] = s;
        c[i] = beta[i] - mean * s;
    }
}

// ---------------- tf32 helpers ----------------------------------------------
__device__ __forceinline__ uint32_t f_tf32(float x) {
    uint32_t y;
    asm("cvt.rna.tf32.f32 %0, %1;" : "=r"(y) : "f"(x));
    return y;
}

#define MMA_TF32(acc, a0, a1, a2, a3, b0, b1)                                  \
    asm volatile(                                                              \
        "mma.sync.aligned.m16n8k8.row.col.f32.tf32.tf32.f32 "                  \
        "{%0,%1,%2,%3}, {%4,%5,%6,%7}, {%8,%9}, {%0,%1,%2,%3};"                \
        : "+f"((acc)[0]), "+f"((acc)[1]), "+f"((acc)[2]), "+f"((acc)[3])       \
        : "r"(a0), "r"(a1), "r"(a2), "r"(a3), "r"(b0), "r"(b1))

// ---------------- tf32 tensor GEMM1: h = x @ W  (M x 128 x 128) -------------
__global__ __launch_bounds__(256) void tgemm1_kernel(
    const float* __restrict__ A, const float* __restrict__ B, float* __restrict__ C, int M) {
    constexpr int BM = 128, BN = 128, BK = 32;
    __shared__ uint32_t As[BM][BK + 4];
    __shared__ uint32_t Bs[BK][BN + 8];

    int tid = threadIdx.x;
    int lane = tid & 31, wid = tid >> 5;
    int wr = wid & 3, wc = wid >> 2;
    int m0 = wr * 32, n0 = wc * 64;
    int row0 = blockIdx.x * BM;
    int grp = lane >> 2, tig = lane & 3;

    float acc[2][8][4];
    #pragma unroll
    for (int i = 0; i < 2; i++)
        #pragma unroll
        for (int j = 0; j < 8; j++)
            #pragma unroll
            for (int r = 0; r < 4; r++) acc[i][j][r] = 0.f;

    for (int k0 = 0; k0 < 128; k0 += BK) {
        #pragma unroll
        for (int p = 0; p < 4; p++) {
            int f = tid + p * 256;
            int r = f >> 3;
            int c4 = (f & 7) * 4;
            float4 v = make_float4(0.f, 0.f, 0.f, 0.f);
            if (row0 + r < M) v = *(const float4*)&A[(size_t)(row0 + r) * 128 + k0 + c4];
            As[r][c4 + 0] = f_tf32(v.x); As[r][c4 + 1] = f_tf32(v.y);
            As[r][c4 + 2] = f_tf32(v.z); As[r][c4 + 3] = f_tf32(v.w);
        }
        #pragma unroll
        for (int p = 0; p < 4; p++) {
            int f = tid + p * 256;
            int kr = f >> 5;
            int c4 = (f & 31) * 4;
            float4 v = *(const float4*)&B[(size_t)(k0 + kr) * 128 + c4];
            Bs[kr][c4 + 0] = f_tf32(v.x); Bs[kr][c4 + 1] = f_tf32(v.y);
            Bs[kr][c4 + 2] = f_tf32(v.z); Bs[kr][c4 + 3] = f_tf32(v.w);
        }
        __syncthreads();

        #pragma unroll
        for (int ks = 0; ks < BK / 8; ks++) {
            int kb = ks * 8;
            uint32_t a[2][4];
            #pragma unroll
            for (int mi = 0; mi < 2; mi++) {
                int r = m0 + mi * 16 + grp;
                a[mi][0] = As[r    ][kb + tig    ];
                a[mi][1] = As[r + 8][kb + tig    ];
                a[mi][2] = As[r    ][kb + tig + 4];
                a[mi][3] = As[r + 8][kb + tig + 4];
            }
            uint32_t b[8][2];
            #pragma unroll
            for (int ni = 0; ni < 8; ni++) {
                int n = n0 + ni * 8 + grp;
                b[ni][0] = Bs[kb + tig    ][n];
                b[ni][1] = Bs[kb + tig + 4][n];
            }
            #pragma unroll
            for (int mi = 0; mi < 2; mi++)
                #pragma unroll
                for (int ni = 0; ni < 8; ni++)
                    MMA_TF32(acc[mi][ni], a[mi][0], a[mi][1], a[mi][2], a[mi][3],
                             b[ni][0], b[ni][1]);
        }
        __syncthreads();
    }

    #pragma unroll
    for (int mi = 0; mi < 2; mi++) {
        int rbase = row0 + m0 + mi * 16 + grp;
        #pragma unroll
        for (int ni = 0; ni < 8; ni++) {
            int col = n0 + ni * 8 + 2 * tig;
            if (rbase < M) {
                float2 v0 = make_float2(acc[mi][ni][0], acc[mi][ni][1]);
                *(float2*)&C[(size_t)rbase * 128 + col] = v0;
            }
            if (rbase + 8 < M) {
                float2 v1 = make_float2(acc[mi][ni][2], acc[mi][ni][3]);
                *(float2*)&C[(size_t)(rbase + 8) * 128 + col] = v1;
            }
        }
    }
}

// ---------------- tf32 tensor GEMM2: t = relu(a*agg+c) @ W1 (M x 128 x 64) --
__global__ __launch_bounds__(256) void tgemm2_kernel(
    const float* __restrict__ A, const float* __restrict__ B, float* __restrict__ C,
    int M, const float* __restrict__ sc, const float* __restrict__ shf) {
    constexpr int BM = 128, BN = 64, BK = 32, K = 128;
    __shared__ uint32_t As[BM][BK + 4];
    __shared__ uint32_t Bs[BK][BN + 8];
    __shared__ float s_sc[K], s_sh[K];

    int tid = threadIdx.x;
    if (tid < K) { s_sc[tid] = sc[tid]; s_sh[tid] = shf[tid]; }

    int lane = tid & 31, wid = tid >> 5;
    int wr = wid & 3, wc = wid >> 2;
    int m0 = wr * 32, n0 = wc * 32;
    int row0 = blockIdx.x * BM;
    int grp = lane >> 2, tig = lane & 3;
    __syncthreads();

    float acc[2][4][4];
    #pragma unroll
    for (int i = 0; i < 2; i++)
        #pragma unroll
        for (int j = 0; j < 4; j++)
            #pragma unroll
            for (int r = 0; r < 4; r++) acc[i][j][r] = 0.f;

    for (int k0 = 0; k0 < K; k0 += BK) {
        #pragma unroll
        for (int p = 0; p < 4; p++) {
            int f = tid + p * 256;
            int r = f >> 3;
            int c4 = (f & 7) * 4;
            float4 v = make_float4(0.f, 0.f, 0.f, 0.f);
            if (row0 + r < M) v = *(const float4*)&A[(size_t)(row0 + r) * K + k0 + c4];
            int kb = k0 + c4;
            v.x = fmaxf(fmaf(v.x, s_sc[kb + 0], s_sh[kb + 0]), 0.f);
            v.y = fmaxf(fmaf(v.y, s_sc[kb + 1], s_sh[kb + 1]), 0.f);
            v.z = fmaxf(fmaf(v.z, s_sc[kb + 2], s_sh[kb + 2]), 0.f);
            v.w = fmaxf(fmaf(v.w, s_sc[kb + 3], s_sh[kb + 3]), 0.f);
            As[r][c4 + 0] = f_tf32(v.x); As[r][c4 + 1] = f_tf32(v.y);
            As[r][c4 + 2] = f_tf32(v.z); As[r][c4 + 3] = f_tf32(v.w);
        }
        #pragma unroll
        for (int p = 0; p < 2; p++) {
            int f = tid + p * 256;
            int kr = f >> 4;
            int c4 = (f & 15) * 4;
            float4 v = *(const float4*)&B[(size_t)(k0 + kr) * BN + c4];
            Bs[kr][c4 + 0] = f_tf32(v.x); Bs[kr][c4 + 1] = f_tf32(v.y);
            Bs[kr][c4 + 2] = f_tf32(v.z); Bs[kr][c4 + 3] = f_tf32(v.w);
        }
        __syncthreads();

        #pragma unroll
        for (int ks = 0; ks < BK / 8; ks++) {
            int kb = ks * 8;
            uint32_t a[2][4];
            #pragma unroll
            for (int mi = 0; mi < 2; mi++) {
                int r = m0 + mi * 16 + grp;
                a[mi][0] = As[r    ][kb + tig    ];
                a[mi][1] = As[r + 8][kb + tig    ];
                a[mi][2] = As[r    ][kb + tig + 4];
                a[mi][3] = As[r + 8][kb + tig + 4];
            }
            uint32_t b[4][2];
            #pragma unroll
            for (int ni = 0; ni < 4; ni++) {
                int n = n0 + ni * 8 + grp;
                b[ni][0] = Bs[kb + tig    ][n];
                b[ni][1] = Bs[kb + tig + 4][n];
            }
            #pragma unroll
            for (int mi = 0; mi < 2; mi++)
                #pragma unroll
                for (int ni = 0; ni < 4; ni++)
                    MMA_TF32(acc[mi][ni], a[mi][0], a[mi][1], a[mi][2], a[mi][3],
                             b[ni][0], b[ni][1]);
        }
        __syncthreads();
    }

    #pragma unroll
    for (int mi = 0; mi < 2; mi++) {
        int rbase = row0 + m0 + mi * 16 + grp;
        #pragma unroll
        for (int ni = 0; ni < 4; ni++) {
            int col = n0 + ni * 8 + 2 * tig;
            if (rbase < M) {
                float2 v0 = make_float2(acc[mi][ni][0], acc[mi][ni][1]);
                *(float2*)&C[(size_t)rbase * BN + col] = v0;
            }
            if (rbase + 8 < M) {
                float2 v1 = make_float2(acc[mi][ni][2], acc[mi][ni][3]);
                *(float2*)&C[(size_t)(rbase + 8) * BN + col] = v1;
            }
        }
    }
}

// ---------------- 3xtf32 tensor GEMM3 (error-compensated, fp32-class) -------
// out = relu(a2*t+c2) @ W2 + b2   (M x 64 x 64)
// a = hi+lo split; acc = hi*hi + lo*hi + hi*lo  (lo*lo dropped, ~2^-22 rel)
__global__ __launch_bounds__(256) void tgemm3_kernel(
    const float* __restrict__ A, const float* __restrict__ B, float* __restrict__ C,
    int M, const float* __restrict__ sc, const float* __restrict__ shf,
    const float* __restrict__ bias) {
    constexpr int BM = 128, BN = 64, BK = 16, K = 64;
    __shared__ uint32_t Ah[BM][BK + 4], Al[BM][BK + 4];   // stride 20: conflict-free frags
    __shared__ uint32_t Bh[BK][BN + 8], Bl[BK][BN + 8];   // stride 72: conflict-free frags
    __shared__ float s_sc[K], s_sh[K], s_b[BN];

    int tid = threadIdx.x;
    if (tid < K) { s_sc[tid] = sc[tid]; s_sh[tid] = shf[tid]; }
    if (tid < BN) s_b[tid] = bias[tid];

    int lane = tid & 31, wid = tid >> 5;
    int wr = wid & 3, wc = wid >> 2;       // warp tile: 32 rows x 32 cols
    int m0 = wr * 32, n0 = wc * 32;
    int row0 = blockIdx.x * BM;
    int grp = lane >> 2, tig = lane & 3;
    __syncthreads();

    float acc[2][4][4];
    #pragma unroll
    for (int i = 0; i < 2; i++)
        #pragma unroll
        for (int j = 0; j < 4; j++)
            #pragma unroll
            for (int r = 0; r < 4; r++) acc[i][j][r] = 0.f;

    for (int k0 = 0; k0 < K; k0 += BK) {
        // A tile 128x16: BN+ReLU then hi/lo split; 512 float4, 2/thread
        #pragma unroll
        for (int p = 0; p < 2; p++) {
            int f = tid + p * 256;
            int r = f >> 2;
            int c4 = (f & 3) * 4;
            float4 v = make_float4(0.f, 0.f, 0.f, 0.f);
            if (row0 + r < M) v = *(const float4*)&A[(size_t)(row0 + r) * K + k0 + c4];
            int kb = k0 + c4;
            v.x = fmaxf(fmaf(v.x, s_sc[kb + 0], s_sh[kb + 0]), 0.f);
            v.y = fmaxf(fmaf(v.y, s_sc[kb + 1], s_sh[kb + 1]), 0.f);
            v.z = fmaxf(fmaf(v.z, s_sc[kb + 2], s_sh[kb + 2]), 0.f);
            v.w = fmaxf(fmaf(v.w, s_sc[kb + 3], s_sh[kb + 3]), 0.f);
            uint32_t hx = f_tf32(v.x), hy = f_tf32(v.y), hz = f_tf32(v.z), hw = f_tf32(v.w);
            Ah[r][c4 + 0] = hx; Ah[r][c4 + 1] = hy; Ah[r][c4 + 2] = hz; Ah[r][c4 + 3] = hw;
            Al[r][c4 + 0] = f_tf32(v.x - __uint_as_float(hx));
            Al[r][c4 + 1] = f_tf32(v.y - __uint_as_float(hy));
            Al[r][c4 + 2] = f_tf32(v.z - __uint_as_float(hz));
            Al[r][c4 + 3] = f_tf32(v.w - __uint_as_float(hw));
        }
        // B tile 16x64: hi/lo split; 256 float4, 1/thread
        {
            int kr = tid >> 4;
            int c4 = (tid & 15) * 4;
            float4 v = *(const float4*)&B[(size_t)(k0 + kr) * BN + c4];
            uint32_t hx = f_tf32(v.x), hy = f_tf32(v.y), hz = f_tf32(v.z), hw = f_tf32(v.w);
            Bh[kr][c4 + 0] = hx; Bh[kr][c4 + 1] = hy; Bh[kr][c4 + 2] = hz; Bh[kr][c4 + 3] = hw;
            Bl[kr][c4 + 0] = f_tf32(v.x - __uint_as_float(hx));
            Bl[kr][c4 + 1] = f_tf32(v.y - __uint_as_float(hy));
            Bl[kr][c4 + 2] = f_tf32(v.z - __uint_as_float(hz));
            Bl[kr][c4 + 3] = f_tf32(v.w - __uint_as_float(hw));
        }
        __syncthreads();

        #pragma unroll
        for (int ks = 0; ks < BK / 8; ks++) {
            int kb = ks * 8;
            uint32_t ah[2][4], al[2][4];
            #pragma unroll
            for (int mi = 0; mi < 2; mi++) {
                int r = m0 + mi * 16 + grp;
                ah[mi][0] = Ah[r    ][kb + tig    ];
                ah[mi][1] = Ah[r + 8][kb + tig    ];
                ah[mi][2] = Ah[r    ][kb + tig + 4];
                ah[mi][3] = Ah[r + 8][kb + tig + 4];
                al[mi][0] = Al[r    ][kb + tig    ];
                al[mi][1] = Al[r + 8][kb + tig    ];
                al[mi][2] = Al[r    ][kb + tig + 4];
                al[mi][3] = Al[r + 8][kb + tig + 4];
            }
            uint32_t bh[4][2], bl[4][2];
            #pragma unroll
            for (int ni = 0; ni < 4; ni++) {
                int n = n0 + ni * 8 + grp;
                bh[ni][0] = Bh[kb + tig    ][n];
                bh[ni][1] = Bh[kb + tig + 4][n];
                bl[ni][0] = Bl[kb + tig    ][n];
                bl[ni][1] = Bl[kb + tig + 4][n];
            }
            #pragma unroll
            for (int mi = 0; mi < 2; mi++)
                #pragma unroll
                for (int ni = 0; ni < 4; ni++) {
                    MMA_TF32(acc[mi][ni], al[mi][0], al[mi][1], al[mi][2], al[mi][3],
                             bh[ni][0], bh[ni][1]);
                    MMA_TF32(acc[mi][ni], ah[mi][0], ah[mi][1], ah[mi][2], ah[mi][3],
                             bl[ni][0], bl[ni][1]);
                    MMA_TF32(acc[mi][ni], ah[mi][0], ah[mi][1], ah[mi][2], ah[mi][3],
                             bh[ni][0], bh[ni][1]);
                }
        }
        __syncthreads();
    }

    #pragma unroll
    for (int mi = 0; mi < 2; mi++) {
        int rbase = row0 + m0 + mi * 16 + grp;
        #pragma unroll
        for (int ni = 0; ni < 4; ni++) {
            int col = n0 + ni * 8 + 2 * tig;
            float b0 = s_b[col], b1 = s_b[col + 1];
            if (rbase < M) {
                float2 v0 = make_float2(acc[mi][ni][0] + b0, acc[mi][ni][1] + b1);
                *(float2*)&C[(size_t)rbase * BN + col] = v0;
            }
            if (rbase + 8 < M) {
                float2 v1 = make_float2(acc[mi][ni][2] + b0, acc[mi][ni][3] + b1);
                *(float2*)&C[(size_t)(rbase + 8) * BN + col] = v1;
            }
        }
    }
}

// ---------------- launch ----------------------------------------------------
extern "C" void kernel_launch(void* const* d_in, const int* in_sizes, int n_in,
                              void* d_out, int out_size) {
    const float* x     = (const float*)d_in[0];
    const int*   ei    = (const int*)d_in[1];
    const float* W_gcn = (const float*)d_in[2];
    // d_in[3] = b_gcn : exactly absorbed by BN1 (mean-subtraction) -> unused
    const float* bn_g  = (const float*)d_in[4];
    const float* bn_b  = (const float*)d_in[5];
    const float* W1    = (const float*)d_in[6];
    // d_in[7] = b1    : exactly absorbed by BN2 -> unused
    const float* mg    = (const float*)d_in[8];
    const float* mb    = (const float*)d_in[9];
    const float* W2    = (const float*)d_in[10];
    const float* b2    = (const float*)d_in[11];
    float* out = (float*)d_out;

    int M = in_sizes[0] / FIN;
    int E = in_sizes[1] / 2;
    const int* src = ei;
    const int* dst = ei + E;

    void *p_h, *p_agg, *p_t, *p_sum1, *p_sq1, *p_a1, *p_c1, *p_sum2, *p_sq2, *p_a2, *p_c2;
    cudaGetSymbolAddress(&p_h, g_h);
    cudaGetSymbolAddress(&p_agg, g_agg);
    cudaGetSymbolAddress(&p_t, g_t);
    cudaGetSymbolAddress(&p_sum1, g_sum1);
    cudaGetSymbolAddress(&p_sq1, g_sq1);
    cudaGetSymbolAddress(&p_a1, g_a1);
    cudaGetSymbolAddress(&p_c1, g_c1);
    cudaGetSymbolAddress(&p_sum2, g_sum2);
    cudaGetSymbolAddress(&p_sq2, g_sq2);
    cudaGetSymbolAddress(&p_a2, g_a2);
    cudaGetSymbolAddress(&p_c2, g_c2);

    // index machinery (4 kernels)
    zero_kernel<<<256, 256>>>(M);
    deg_kernel<<<(E + 255) / 256, 256>>>(dst, E, M);
    alloc_kernel<<<(M + 255) / 256, 256>>>(M);
    fill_kernel<<<(E + 255) / 256, 256>>>(src, dst, E, M);

    // GEMM1 (tf32 tensor cores): h = x @ W_gcn
    tgemm1_kernel<<<(M + 127) / 128, 256>>>(x, W_gcn, (float*)p_h, M);

    // CSR gather
    gather_kernel<<<(M * 32 + 255) / 256, 256>>>(M);

    // BN1 stats
    stats_kernel<FIN><<<1024, 256>>>((const float*)p_agg, M, (float*)p_sum1, (float*)p_sq1);
    finalize_kernel<FIN><<<1, 128>>>((const float*)p_sum1, (const float*)p_sq1,
                                     bn_g, bn_b, M, (float*)p_a1, (float*)p_c1);

    // GEMM2 (tf32 tensor cores): t = relu(BN1(agg)) @ W1  (b1 absorbed by BN2)
    tgemm2_kernel<<<(M + 127) / 128, 256>>>(
        (const float*)p_agg, W1, (float*)p_t, M,
        (const float*)p_a1, (const float*)p_c1);

    // BN2 stats
    stats_kernel<FOUT><<<1024, 256>>>((const float*)p_t, M, (float*)p_sum2, (float*)p_sq2);
    finalize_kernel<FOUT><<<1, 64>>>((const float*)p_sum2, (const float*)p_sq2,
                                     mg, mb, M, (float*)p_a2, (float*)p_c2);

    // GEMM3 (3xtf32, fp32-class accuracy): out = relu(BN2(t)) @ W2 + b2
    tgemm3_kernel<<<(M + 127) / 128, 256>>>(
        (const float*)p_t, W2, out, M,
        (const float*)p_a2, (const float*)p_c2, b2);
}

// round 13
// speedup vs baseline: 1.1427x; 1.0663x over previous
#include <cuda_runtime.h>
#include <cstdint>

#define NNODES 100000
#define NEDGES 640000
#define FIN 128
#define FOUT 64
#define BN_EPS 1e-5f

// ---------------- scratch (static device globals; no runtime allocation) ----
__device__ float g_h[(size_t)NNODES * FIN];     // x @ W_gcn
__device__ float g_agg[(size_t)NNODES * FIN];   // aggregated messages
__device__ float g_t[(size_t)NNODES * FOUT];    // hidden after GEMM2
__device__ int   g_degi[NNODES];
__device__ float g_dinv[NNODES];
__device__ int   g_off[NNODES + 1];
__device__ int   g_cursor[NNODES];
__device__ int   g_alloc;
__device__ int   g_elist[NEDGES];
__device__ float g_sum1[FIN], g_sq1[FIN], g_a1[FIN], g_c1[FIN];
__device__ float g_sum2[FOUT], g_sq2[FOUT], g_a2[FOUT], g_c2[FOUT];

// ---------------- zero ------------------------------------------------------
__global__ void zero_kernel(int M) {
    int i = blockIdx.x * blockDim.x + threadIdx.x;
    for (int j = i; j < M; j += gridDim.x * blockDim.x) g_degi[j] = 0;
    if (i < FIN)  { g_sum1[i] = 0.f; g_sq1[i] = 0.f; }
    if (i < FOUT) { g_sum2[i] = 0.f; g_sq2[i] = 0.f; }
    if (i == 0) g_alloc = 0;
}

// ---------------- in-degree count -------------------------------------------
__global__ void deg_kernel(const int* __restrict__ dst, int E, int M) {
    int e = blockIdx.x * blockDim.x + threadIdx.x;
    if (e < E) {
        int d = dst[e];
        if ((unsigned)d < (unsigned)M) atomicAdd(&g_degi[d], 1);
    }
}

// ---------------- CSR segment allocation (warp-aggregated) ------------------
__global__ void alloc_kernel(int M) {
    int i = blockIdx.x * blockDim.x + threadIdx.x;
    int lane = threadIdx.x & 31;
    int deg = 0;
    if (i < M) deg = g_degi[i];
    int incl = deg;
    #pragma unroll
    for (int o = 1; o < 32; o <<= 1) {
        int v = __shfl_up_sync(0xffffffffu, incl, o);
        if (lane >= o) incl += v;
    }
    int total = __shfl_sync(0xffffffffu, incl, 31);
    int base = 0;
    if (lane == 0) base = atomicAdd(&g_alloc, total);
    base = __shfl_sync(0xffffffffu, base, 0);
    if (i < M) {
        int o = base + incl - deg;
        g_off[i] = o;
        g_cursor[i] = o;
        g_dinv[i] = rsqrtf((float)deg + 1.0f);  // +1 = self loop
    }
}

// ---------------- edge-list fill --------------------------------------------
__global__ void fill_kernel(const int* __restrict__ src, const int* __restrict__ dst,
                            int E, int M) {
    int e = blockIdx.x * blockDim.x + threadIdx.x;
    if (e < E) {
        int s = src[e];
        int d = dst[e];
        if ((unsigned)s < (unsigned)M && (unsigned)d < (unsigned)M) {
            int p = atomicAdd(&g_cursor[d], 1);
            g_elist[p] = s;
        }
    }
}

// ---------------- gather (R4 exact) -----------------------------------------
__global__ void gather_kernel(int M) {
    int warp = (blockIdx.x * blockDim.x + threadIdx.x) >> 5;
    int lane = threadIdx.x & 31;
    if (warp >= M) return;
    int d = warp;
    int e0 = g_off[d];
    int e1 = g_cursor[d];
    float4 acc = make_float4(0.f, 0.f, 0.f, 0.f);
    for (int e = e0; e < e1; e++) {
        int s = g_elist[e];
        float ws = g_dinv[s];
        float4 v = *(const float4*)&g_h[(size_t)s * FIN + lane * 4];
        acc.x = fmaf(v.x, ws, acc.x);
        acc.y = fmaf(v.y, ws, acc.y);
        acc.z = fmaf(v.z, ws, acc.z);
        acc.w = fmaf(v.w, ws, acc.w);
    }
    float wd = g_dinv[d];
    float4 vs = *(const float4*)&g_h[(size_t)d * FIN + lane * 4];
    float4 o;
    o.x = wd * acc.x + wd * wd * vs.x;
    o.y = wd * acc.y + wd * wd * vs.y;
    o.z = wd * acc.z + wd * wd * vs.z;
    o.w = wd * acc.w + wd * wd * vs.w;
    *(float4*)&g_agg[(size_t)d * FIN + lane * 4] = o;
}

// ---------------- per-column sum / sumsq ------------------------------------
template <int F>
__global__ void stats_kernel(const float* __restrict__ X, int M,
                             float* __restrict__ sum, float* __restrict__ sq) {
    constexpr int RP = 256 / F;
    int col  = threadIdx.x % F;
    int rsub = threadIdx.x / F;
    float s = 0.f, q = 0.f;
    for (int r = blockIdx.x * RP + rsub; r < M; r += gridDim.x * RP) {
        float v = X[(size_t)r * F + col];
        s += v; q += v * v;
    }
    __shared__ float sh[256];
    sh[threadIdx.x] = s; __syncthreads();
    if (rsub == 0) {
        #pragma unroll
        for (int k = 1; k < RP; k++) s += sh[k * F + col];
    }
    __syncthreads();
    sh[threadIdx.x] = q; __syncthreads();
    if (rsub == 0) {
        #pragma unroll
        for (int k = 1; k < RP; k++) q += sh[k * F + col];
        atomicAdd(&sum[col], s);
        atomicAdd(&sq[col],  q);
    }
}

template <int F>
__global__ void finalize_kernel(const float* __restrict__ sum, const float* __restrict__ sq,
                                const float* __restrict__ gamma, const float* __restrict__ beta,
                                int M, float* __restrict__ a, float* __restrict__ c) {
    int i = threadIdx.x;
    if (i < F) {
        float mean = sum[i] / (float)M;
        float var  = sq[i] / (float)M - mean * mean;
        float s = gamma[i] * rsqrtf(var + BN_EPS);
        a[i] = s;
        c[i] = beta[i] - mean * s;
    }
}

// ---------------- tf32 helpers ----------------------------------------------
__device__ __forceinline__ uint32_t f_tf32(float x) {
    uint32_t y;
    asm("cvt.rna.tf32.f32 %0, %1;" : "=r"(y) : "f"(x));
    return y;
}

#define MMA_TF32(acc, a0, a1, a2, a3, b0, b1)                                  \
    asm volatile(                                                              \
        "mma.sync.aligned.m16n8k8.row.col.f32.tf32.tf32.f32 "                  \
        "{%0,%1,%2,%3}, {%4,%5,%6,%7}, {%8,%9}, {%0,%1,%2,%3};"                \
        : "+f"((acc)[0]), "+f"((acc)[1]), "+f"((acc)[2]), "+f"((acc)[3])       \
        : "r"(a0), "r"(a1), "r"(a2), "r"(a3), "r"(b0), "r"(b1))

// ---------------- tf32 tensor GEMM1: h = x @ W  (M x 128 x 128) -------------
__global__ __launch_bounds__(256) void tgemm1_kernel(
    const float* __restrict__ A, const float* __restrict__ B, float* __restrict__ C, int M) {
    constexpr int BM = 128, BN = 128, BK = 32;
    __shared__ uint32_t As[BM][BK + 4];
    __shared__ uint32_t Bs[BK][BN + 8];

    int tid = threadIdx.x;
    int lane = tid & 31, wid = tid >> 5;
    int wr = wid & 3, wc = wid >> 2;
    int m0 = wr * 32, n0 = wc * 64;
    int row0 = blockIdx.x * BM;
    int grp = lane >> 2, tig = lane & 3;

    float acc[2][8][4];
    #pragma unroll
    for (int i = 0; i < 2; i++)
        #pragma unroll
        for (int j = 0; j < 8; j++)
            #pragma unroll
            for (int r = 0; r < 4; r++) acc[i][j][r] = 0.f;

    for (int k0 = 0; k0 < 128; k0 += BK) {
        #pragma unroll
        for (int p = 0; p < 4; p++) {
            int f = tid + p * 256;
            int r = f >> 3;
            int c4 = (f & 7) * 4;
            float4 v = make_float4(0.f, 0.f, 0.f, 0.f);
            if (row0 + r < M) v = *(const float4*)&A[(size_t)(row0 + r) * 128 + k0 + c4];
            As[r][c4 + 0] = f_tf32(v.x); As[r][c4 + 1] = f_tf32(v.y);
            As[r][c4 + 2] = f_tf32(v.z); As[r][c4 + 3] = f_tf32(v.w);
        }
        #pragma unroll
        for (int p = 0; p < 4; p++) {
            int f = tid + p * 256;
            int kr = f >> 5;
            int c4 = (f & 31) * 4;
            float4 v = *(const float4*)&B[(size_t)(k0 + kr) * 128 + c4];
            Bs[kr][c4 + 0] = f_tf32(v.x); Bs[kr][c4 + 1] = f_tf32(v.y);
            Bs[kr][c4 + 2] = f_tf32(v.z); Bs[kr][c4 + 3] = f_tf32(v.w);
        }
        __syncthreads();

        #pragma unroll
        for (int ks = 0; ks < BK / 8; ks++) {
            int kb = ks * 8;
            uint32_t a[2][4];
            #pragma unroll
            for (int mi = 0; mi < 2; mi++) {
                int r = m0 + mi * 16 + grp;
                a[mi][0] = As[r    ][kb + tig    ];
                a[mi][1] = As[r + 8][kb + tig    ];
                a[mi][2] = As[r    ][kb + tig + 4];
                a[mi][3] = As[r + 8][kb + tig + 4];
            }
            uint32_t b[8][2];
            #pragma unroll
            for (int ni = 0; ni < 8; ni++) {
                int n = n0 + ni * 8 + grp;
                b[ni][0] = Bs[kb + tig    ][n];
                b[ni][1] = Bs[kb + tig + 4][n];
            }
            #pragma unroll
            for (int mi = 0; mi < 2; mi++)
                #pragma unroll
                for (int ni = 0; ni < 8; ni++)
                    MMA_TF32(acc[mi][ni], a[mi][0], a[mi][1], a[mi][2], a[mi][3],
                             b[ni][0], b[ni][1]);
        }
        __syncthreads();
    }

    #pragma unroll
    for (int mi = 0; mi < 2; mi++) {
        int rbase = row0 + m0 + mi * 16 + grp;
        #pragma unroll
        for (int ni = 0; ni < 8; ni++) {
            int col = n0 + ni * 8 + 2 * tig;
            if (rbase < M) {
                float2 v0 = make_float2(acc[mi][ni][0], acc[mi][ni][1]);
                *(float2*)&C[(size_t)rbase * 128 + col] = v0;
            }
            if (rbase + 8 < M) {
                float2 v1 = make_float2(acc[mi][ni][2], acc[mi][ni][3]);
                *(float2*)&C[(size_t)(rbase + 8) * 128 + col] = v1;
            }
        }
    }
}

// ---------------- tf32 tensor GEMM2: t = relu(a*agg+c) @ W1 (M x 128 x 64) --
__global__ __launch_bounds__(256) void tgemm2_kernel(
    const float* __restrict__ A, const float* __restrict__ B, float* __restrict__ C,
    int M, const float* __restrict__ sc, const float* __restrict__ shf) {
    constexpr int BM = 128, BN = 64, BK = 32, K = 128;
    __shared__ uint32_t As[BM][BK + 4];
    __shared__ uint32_t Bs[BK][BN + 8];
    __shared__ float s_sc[K], s_sh[K];

    int tid = threadIdx.x;
    if (tid < K) { s_sc[tid] = sc[tid]; s_sh[tid] = shf[tid]; }

    int lane = tid & 31, wid = tid >> 5;
    int wr = wid & 3, wc = wid >> 2;
    int m0 = wr * 32, n0 = wc * 32;
    int row0 = blockIdx.x * BM;
    int grp = lane >> 2, tig = lane & 3;
    __syncthreads();

    float acc[2][4][4];
    #pragma unroll
    for (int i = 0; i < 2; i++)
        #pragma unroll
        for (int j = 0; j < 4; j++)
            #pragma unroll
            for (int r = 0; r < 4; r++) acc[i][j][r] = 0.f;

    for (int k0 = 0; k0 < K; k0 += BK) {
        #pragma unroll
        for (int p = 0; p < 4; p++) {
            int f = tid + p * 256;
            int r = f >> 3;
            int c4 = (f & 7) * 4;
            float4 v = make_float4(0.f, 0.f, 0.f, 0.f);
            if (row0 + r < M) v = *(const float4*)&A[(size_t)(row0 + r) * K + k0 + c4];
            int kb = k0 + c4;
            v.x = fmaxf(fmaf(v.x, s_sc[kb + 0], s_sh[kb + 0]), 0.f);
            v.y = fmaxf(fmaf(v.y, s_sc[kb + 1], s_sh[kb + 1]), 0.f);
            v.z = fmaxf(fmaf(v.z, s_sc[kb + 2], s_sh[kb + 2]), 0.f);
            v.w = fmaxf(fmaf(v.w, s_sc[kb + 3], s_sh[kb + 3]), 0.f);
            As[r][c4 + 0] = f_tf32(v.x); As[r][c4 + 1] = f_tf32(v.y);
            As[r][c4 + 2] = f_tf32(v.z); As[r][c4 + 3] = f_tf32(v.w);
        }
        #pragma unroll
        for (int p = 0; p < 2; p++) {
            int f = tid + p * 256;
            int kr = f >> 4;
            int c4 = (f & 15) * 4;
            float4 v = *(const float4*)&B[(size_t)(k0 + kr) * BN + c4];
            Bs[kr][c4 + 0] = f_tf32(v.x); Bs[kr][c4 + 1] = f_tf32(v.y);
            Bs[kr][c4 + 2] = f_tf32(v.z); Bs[kr][c4 + 3] = f_tf32(v.w);
        }
        __syncthreads();

        #pragma unroll
        for (int ks = 0; ks < BK / 8; ks++) {
            int kb = ks * 8;
            uint32_t a[2][4];
            #pragma unroll
            for (int mi = 0; mi < 2; mi++) {
                int r = m0 + mi * 16 + grp;
                a[mi][0] = As[r    ][kb + tig    ];
                a[mi][1] = As[r + 8][kb + tig    ];
                a[mi][2] = As[r    ][kb + tig + 4];
                a[mi][3] = As[r + 8][kb + tig + 4];
            }
            uint32_t b[4][2];
            #pragma unroll
            for (int ni = 0; ni < 4; ni++) {
                int n = n0 + ni * 8 + grp;
                b[ni][0] = Bs[kb + tig    ][n];
                b[ni][1] = Bs[kb + tig + 4][n];
            }
            #pragma unroll
            for (int mi = 0; mi < 2; mi++)
                #pragma unroll
                for (int ni = 0; ni < 4; ni++)
                    MMA_TF32(acc[mi][ni], a[mi][0], a[mi][1], a[mi][2], a[mi][3],
                             b[ni][0], b[ni][1]);
        }
        __syncthreads();
    }

    #pragma unroll
    for (int mi = 0; mi < 2; mi++) {
        int rbase = row0 + m0 + mi * 16 + grp;
        #pragma unroll
        for (int ni = 0; ni < 4; ni++) {
            int col = n0 + ni * 8 + 2 * tig;
            if (rbase < M) {
                float2 v0 = make_float2(acc[mi][ni][0], acc[mi][ni][1]);
                *(float2*)&C[(size_t)rbase * BN + col] = v0;
            }
            if (rbase + 8 < M) {
                float2 v1 = make_float2(acc[mi][ni][2], acc[mi][ni][3]);
                *(float2*)&C[(size_t)(rbase + 8) * BN + col] = v1;
            }
        }
    }
}

// ---------------- 3xtf32 tensor GEMM3 (error-compensated, fp32-class) -------
__global__ __launch_bounds__(256) void tgemm3_kernel(
    const float* __restrict__ A, const float* __restrict__ B, float* __restrict__ C,
    int M, const float* __restrict__ sc, const float* __restrict__ shf,
    const float* __restrict__ bias) {
    constexpr int BM = 128, BN = 64, BK = 16, K = 64;
    __shared__ uint32_t Ah[BM][BK + 4], Al[BM][BK + 4];
    __shared__ uint32_t Bh[BK][BN + 8], Bl[BK][BN + 8];
    __shared__ float s_sc[K], s_sh[K], s_b[BN];

    int tid = threadIdx.x;
    if (tid < K) { s_sc[tid] = sc[tid]; s_sh[tid] = shf[tid]; }
    if (tid < BN) s_b[tid] = bias[tid];

    int lane = tid & 31, wid = tid >> 5;
    int wr = wid & 3, wc = wid >> 2;
    int m0 = wr * 32, n0 = wc * 32;
    int row0 = blockIdx.x * BM;
    int grp = lane >> 2, tig = lane & 3;
    __syncthreads();

    float acc[2][4][4];
    #pragma unroll
    for (int i = 0; i < 2; i++)
        #pragma unroll
        for (int j = 0; j < 4; j++)
            #pragma unroll
            for (int r = 0; r < 4; r++) acc[i][j][r] = 0.f;

    for (int k0 = 0; k0 < K; k0 += BK) {
        #pragma unroll
        for (int p = 0; p < 2; p++) {
            int f = tid + p * 256;
            int r = f >> 2;
            int c4 = (f & 3) * 4;
            float4 v = make_float4(0.f, 0.f, 0.f, 0.f);
            if (row0 + r < M) v = *(const float4*)&A[(size_t)(row0 + r) * K + k0 + c4];
            int kb = k0 + c4;
            v.x = fmaxf(fmaf(v.x, s_sc[kb + 0], s_sh[kb + 0]), 0.f);
            v.y = fmaxf(fmaf(v.y, s_sc[kb + 1], s_sh[kb + 1]), 0.f);
            v.z = fmaxf(fmaf(v.z, s_sc[kb + 2], s_sh[kb + 2]), 0.f);
            v.w = fmaxf(fmaf(v.w, s_sc[kb + 3], s_sh[kb + 3]), 0.f);
            uint32_t hx = f_tf32(v.x), hy = f_tf32(v.y), hz = f_tf32(v.z), hw = f_tf32(v.w);
            Ah[r][c4 + 0] = hx; Ah[r][c4 + 1] = hy; Ah[r][c4 + 2] = hz; Ah[r][c4 + 3] = hw;
            Al[r][c4 + 0] = f_tf32(v.x - __uint_as_float(hx));
            Al[r][c4 + 1] = f_tf32(v.y - __uint_as_float(hy));
            Al[r][c4 + 2] = f_tf32(v.z - __uint_as_float(hz));
            Al[r][c4 + 3] = f_tf32(v.w - __uint_as_float(hw));
        }
        {
            int kr = tid >> 4;
            int c4 = (tid & 15) * 4;
            float4 v = *(const float4*)&B[(size_t)(k0 + kr) * BN + c4];
            uint32_t hx = f_tf32(v.x), hy = f_tf32(v.y), hz = f_tf32(v.z), hw = f_tf32(v.w);
            Bh[kr][c4 + 0] = hx; Bh[kr][c4 + 1] = hy; Bh[kr][c4 + 2] = hz; Bh[kr][c4 + 3] = hw;
            Bl[kr][c4 + 0] = f_tf32(v.x - __uint_as_float(hx));
            Bl[kr][c4 + 1] = f_tf32(v.y - __uint_as_float(hy));
            Bl[kr][c4 + 2] = f_tf32(v.z - __uint_as_float(hz));
            Bl[kr][c4 + 3] = f_tf32(v.w - __uint_as_float(hw));
        }
        __syncthreads();

        #pragma unroll
        for (int ks = 0; ks < BK / 8; ks++) {
            int kb = ks * 8;
            uint32_t ah[2][4], al[2][4];
            #pragma unroll
            for (int mi = 0; mi < 2; mi++) {
                int r = m0 + mi * 16 + grp;
                ah[mi][0] = Ah[r    ][kb + tig    ];
                ah[mi][1] = Ah[r + 8][kb + tig    ];
                ah[mi][2] = Ah[r    ][kb + tig + 4];
                ah[mi][3] = Ah[r + 8][kb + tig + 4];
                al[mi][0] = Al[r    ][kb + tig    ];
                al[mi][1] = Al[r + 8][kb + tig    ];
                al[mi][2] = Al[r    ][kb + tig + 4];
                al[mi][3] = Al[r + 8][kb + tig + 4];
            }
            uint32_t bh[4][2], bl[4][2];
            #pragma unroll
            for (int ni = 0; ni < 4; ni++) {
                int n = n0 + ni * 8 + grp;
                bh[ni][0] = Bh[kb + tig    ][n];
                bh[ni][1] = Bh[kb + tig + 4][n];
                bl[ni][0] = Bl[kb + tig    ][n];
                bl[ni][1] = Bl[kb + tig + 4][n];
            }
            #pragma unroll
            for (int mi = 0; mi < 2; mi++)
                #pragma unroll
                for (int ni = 0; ni < 4; ni++) {
                    MMA_TF32(acc[mi][ni], al[mi][0], al[mi][1], al[mi][2], al[mi][3],
                             bh[ni][0], bh[ni][1]);
                    MMA_TF32(acc[mi][ni], ah[mi][0], ah[mi][1], ah[mi][2], ah[mi][3],
                             bl[ni][0], bl[ni][1]);
                    MMA_TF32(acc[mi][ni], ah[mi][0], ah[mi][1], ah[mi][2], ah[mi][3],
                             bh[ni][0], bh[ni][1]);
                }
        }
        __syncthreads();
    }

    #pragma unroll
    for (int mi = 0; mi < 2; mi++) {
        int rbase = row0 + m0 + mi * 16 + grp;
        #pragma unroll
        for (int ni = 0; ni < 4; ni++) {
            int col = n0 + ni * 8 + 2 * tig;
            float b0 = s_b[col], b1 = s_b[col + 1];
            if (rbase < M) {
                float2 v0 = make_float2(acc[mi][ni][0] + b0, acc[mi][ni][1] + b1);
                *(float2*)&C[(size_t)rbase * BN + col] = v0;
            }
            if (rbase + 8 < M) {
                float2 v1 = make_float2(acc[mi][ni][2] + b0, acc[mi][ni][3] + b1);
                *(float2*)&C[(size_t)(rbase + 8) * BN + col] = v1;
            }
        }
    }
}

// ---------------- launch ----------------------------------------------------
extern "C" void kernel_launch(void* const* d_in, const int* in_sizes, int n_in,
                              void* d_out, int out_size) {
    const float* x     = (const float*)d_in[0];
    const int*   ei    = (const int*)d_in[1];
    const float* W_gcn = (const float*)d_in[2];
    // d_in[3] = b_gcn : exactly absorbed by BN1 (mean-subtraction) -> unused
    const float* bn_g  = (const float*)d_in[4];
    const float* bn_b  = (const float*)d_in[5];
    const float* W1    = (const float*)d_in[6];
    // d_in[7] = b1    : exactly absorbed by BN2 -> unused
    const float* mg    = (const float*)d_in[8];
    const float* mb    = (const float*)d_in[9];
    const float* W2    = (const float*)d_in[10];
    const float* b2    = (const float*)d_in[11];
    float* out = (float*)d_out;

    int M = in_sizes[0] / FIN;
    int E = in_sizes[1] / 2;
    const int* src = ei;
    const int* dst = ei + E;

    void *p_h, *p_agg, *p_t, *p_sum1, *p_sq1, *p_a1, *p_c1, *p_sum2, *p_sq2, *p_a2, *p_c2;
    cudaGetSymbolAddress(&p_h, g_h);
    cudaGetSymbolAddress(&p_agg, g_agg);
    cudaGetSymbolAddress(&p_t, g_t);
    cudaGetSymbolAddress(&p_sum1, g_sum1);
    cudaGetSymbolAddress(&p_sq1, g_sq1);
    cudaGetSymbolAddress(&p_a1, g_a1);
    cudaGetSymbolAddress(&p_c1, g_c1);
    cudaGetSymbolAddress(&p_sum2, g_sum2);
    cudaGetSymbolAddress(&p_sq2, g_sq2);
    cudaGetSymbolAddress(&p_a2, g_a2);
    cudaGetSymbolAddress(&p_c2, g_c2);

    // side stream + fork/join events; created once on the first (uncaptured)
    // correctness call, reused for every call -> identical work each launch.
    static cudaStream_t s_side = nullptr;
    static cudaEvent_t s_evFork = nullptr, s_evJoin = nullptr;
    if (s_side == nullptr) {
        cudaStreamCreateWithFlags(&s_side, cudaStreamNonBlocking);
        cudaEventCreateWithFlags(&s_evFork, cudaEventDisableTiming);
        cudaEventCreateWithFlags(&s_evJoin, cudaEventDisableTiming);
    }

    // main: zero (needed by both branches)
    zero_kernel<<<256, 256>>>(M);

    // fork: index machinery on side stream, overlapped with tgemm1 on main
    cudaEventRecord(s_evFork, 0);
    cudaStreamWaitEvent(s_side, s_evFork, 0);
    deg_kernel<<<(E + 255) / 256, 256, 0, s_side>>>(dst, E, M);
    alloc_kernel<<<(M + 255) / 256, 256, 0, s_side>>>(M);
    fill_kernel<<<(E + 255) / 256, 256, 0, s_side>>>(src, dst, E, M);
    cudaEventRecord(s_evJoin, s_side);

    // main: GEMM1 (tf32): h = x @ W_gcn  (independent of index machinery)
    tgemm1_kernel<<<(M + 127) / 128, 256>>>(x, W_gcn, (float*)p_h, M);

    // join: gather needs h + CSR + dinv
    cudaStreamWaitEvent(0, s_evJoin, 0);
    gather_kernel<<<(M * 32 + 255) / 256, 256>>>(M);

    // BN1 stats
    stats_kernel<FIN><<<1024, 256>>>((const float*)p_agg, M, (float*)p_sum1, (float*)p_sq1);
    finalize_kernel<FIN><<<1, 128>>>((const float*)p_sum1, (const float*)p_sq1,
                                     bn_g, bn_b, M, (float*)p_a1, (float*)p_c1);

    // GEMM2 (tf32): t = relu(BN1(agg)) @ W1  (b1 absorbed by BN2)
    tgemm2_kernel<<<(M + 127) / 128, 256>>>(
        (const float*)p_agg, W1, (float*)p_t, M,
        (const float*)p_a1, (const float*)p_c1);

    // BN2 stats
    stats_kernel<FOUT><<<1024, 256>>>((const float*)p_t, M, (float*)p_sum2, (float*)p_sq2);
    finalize_kernel<FOUT><<<1, 64>>>((const float*)p_sum2, (const float*)p_sq2,
                                     mg, mb, M, (float*)p_a2, (float*)p_c2);

    // GEMM3 (3xtf32, fp32-class): out = relu(BN2(t)) @ W2 + b2
    tgemm3_kernel<<<(M + 127) / 128, 256>>>(
        (const float*)p_t, W2, out, M,
        (const float*)p_a2, (const float*)p_c2, b2);
}